// round 9
// baseline (speedup 1.0000x reference)
#include <cuda_runtime.h>
#include <cuda_bf16.h>
#include <mma.h>
#include <cstdint>
#include <math.h>

using namespace nvcuda;

#define NN 100000
#define EE 1600000

// ---------------- scratch (device globals; no runtime allocation) ----------------
__device__ int   g_deg[NN];
__device__ int   g_rowp[NN + 1];
__device__ int   g_cur[NN];
__device__ int   g_esrc[EE];
__device__ float g_dinv[NN];
__device__ float g_mu[NN];
__device__ float g_rs[NN];
__device__ float g_sA[NN];
__device__ float g_sA2[NN];
__device__ float g_t [NN * 128];
__device__ float g_h1[NN * 128];
__device__ float g_h2[NN * 128];
__device__ float g_t2[NN * 64];
// packed bf16-split weights: per chunk [hi 32*NPADP][lo 32*NPADP]
__device__ __align__(16) __nv_bfloat16 g_wb0[20 * 2 * 32 * 136];
__device__ __align__(16) __nv_bfloat16 g_wb1[20 * 2 * 32 * 136];
__device__ __align__(16) __nv_bfloat16 g_wb2[60 * 2 * 32 * 56];

// ---------------- async-copy helpers ----------------
__device__ __forceinline__ uint32_t smem_u32(const void* p) {
    uint32_t a;
    asm("{ .reg .u64 t; cvta.to.shared.u64 t, %1; cvt.u32.u64 %0, t; }"
        : "=r"(a) : "l"(p));
    return a;
}
__device__ __forceinline__ void cpasync16(uint32_t dst, const void* src) {
    asm volatile("cp.async.cg.shared.global [%0], [%1], 16;" :: "r"(dst), "l"(src));
}
#define CPCOMMIT() asm volatile("cp.async.commit_group;" ::: "memory")
#define CPWAIT0()  asm volatile("cp.async.wait_group 0;" ::: "memory")

// ---------------- graph preprocessing ----------------
__global__ void k_zero_deg() {
    int i = blockIdx.x * blockDim.x + threadIdx.x;
    if (i < NN) g_deg[i] = 0;
}
__global__ void k_count(const int* __restrict__ ei) {
    int e = blockIdx.x * blockDim.x + threadIdx.x;
    if (e < EE) atomicAdd(&g_deg[ei[EE + e]], 1);
}
__global__ void k_scan() {
    __shared__ int wsum[32];
    __shared__ int scarry;
    int t = threadIdx.x, lane = t & 31, wid = t >> 5;
    if (t == 0) scarry = 0;
    __syncthreads();
    for (int base = 0; base < NN; base += 1024) {
        int i = base + t;
        int v = (i < NN) ? g_deg[i] : 0;
        int x = v;
        #pragma unroll
        for (int d = 1; d < 32; d <<= 1) {
            int y = __shfl_up_sync(0xffffffffu, x, d);
            if (lane >= d) x += y;
        }
        if (lane == 31) wsum[wid] = x;
        __syncthreads();
        if (wid == 0) {
            int ws = wsum[lane];
            #pragma unroll
            for (int d = 1; d < 32; d <<= 1) {
                int y = __shfl_up_sync(0xffffffffu, ws, d);
                if (lane >= d) ws += y;
            }
            wsum[lane] = ws;
        }
        __syncthreads();
        int carry = scarry;
        int excl = carry + (wid ? wsum[wid - 1] : 0) + (x - v);
        if (i < NN) { g_rowp[i] = excl; g_cur[i] = excl; }
        __syncthreads();
        if (t == 0) scarry = carry + wsum[31];
        __syncthreads();
    }
    if (t == 0) g_rowp[NN] = scarry;
}
__global__ void k_dinv() {
    int i = blockIdx.x * blockDim.x + threadIdx.x;
    if (i < NN) g_dinv[i] = rsqrtf((float)(g_deg[i] + 1));
}
__global__ void k_place(const int* __restrict__ ei) {
    int e = blockIdx.x * blockDim.x + threadIdx.x;
    if (e < EE) {
        int d = ei[EE + e];
        int pos = atomicAdd(&g_cur[d], 1);
        g_esrc[pos] = ei[e];
    }
}

// ---------------- weight precompute: bf16 hi/lo, chunk-packed ----------------
template<int DIN, int DOUT, int NPAD, int NPADP>
__global__ void k_prepw(const float* __restrict__ Wb, const float* __restrict__ Ws,
                        __nv_bfloat16* __restrict__ dst) {
    constexpr int NCH = DIN * 5 / 32;
    int idx = blockIdx.x * blockDim.x + threadIdx.x;
    if (idx >= NCH * 2 * 32 * NPADP) return;
    int n = idx % NPADP;
    int k = (idx / NPADP) & 31;
    int h = (idx / (NPADP * 32)) & 1;
    int c = idx / (NPADP * 32 * 2);
    int kg = c * 32 + k;
    float w = 0.f;
    if (n < DOUT) {
        if (kg < DIN) w = Wb[(size_t)n * DIN + kg];
        else          w = Ws[(size_t)n * (DIN * 4) + (kg - DIN)];
    }
    __nv_bfloat16 hi = __float2bfloat16(w);
    __nv_bfloat16 lo = __float2bfloat16(w - __bfloat162float(hi));
    dst[idx] = h ? lo : hi;
}

// ---------------- stats of x (warp per node): mu0/rs0 + partials ----------------
__global__ void k_statx(const float* __restrict__ x) {
    int gw = (blockIdx.x * blockDim.x + threadIdx.x) >> 5;
    int lane = threadIdx.x & 31;
    if (gw >= NN) return;
    float4 v = ((const float4*)(x + (size_t)gw * 128))[lane];
    float s  = v.x + v.y + v.z + v.w;
    float s2 = v.x * v.x + v.y * v.y + v.z * v.z + v.w * v.w;
    #pragma unroll
    for (int d = 16; d; d >>= 1) {
        s  += __shfl_xor_sync(0xffffffffu, s,  d);
        s2 += __shfl_xor_sync(0xffffffffu, s2, d);
    }
    if (lane == 0) {
        float m = s * (1.f / 128.f);
        g_mu[gw] = m;
        g_rs[gw] = rsqrtf(s2 * (1.f / 128.f) - m * m + 1e-5f);
        g_sA[gw]  = s;
        g_sA2[gw] = s2;
    }
}

// ---------------- fused FastKAN layer via wmma bf16 (3-term compensation) ----------------
template<int DIN>
__device__ __forceinline__ float4 ldx4(const float* __restrict__ a,
                                       const float* __restrict__ b,
                                       const float* __restrict__ c,
                                       int n, int col) {
    if (DIN == 128) return *(const float4*)(a + (size_t)n * 128 + col);
    const float* p = (col < 128) ? a : (col < 256) ? b : c;
    return *(const float4*)(p + (size_t)n * 128 + (col & 127));
}

__device__ __forceinline__ void splitstore(__nv_bfloat16* hiP, __nv_bfloat16* loP,
                                           float4 v) {
    __nv_bfloat162 h0 = __floats2bfloat162_rn(v.x, v.y);
    __nv_bfloat162 h1 = __floats2bfloat162_rn(v.z, v.w);
    float2 f0 = __bfloat1622float2(h0);
    float2 f1 = __bfloat1622float2(h1);
    __nv_bfloat162 l0 = __floats2bfloat162_rn(v.x - f0.x, v.y - f0.y);
    __nv_bfloat162 l1 = __floats2bfloat162_rn(v.z - f1.x, v.w - f1.y);
    ((__nv_bfloat162*)hiP)[0] = h0;
    ((__nv_bfloat162*)hiP)[1] = h1;
    ((__nv_bfloat162*)loP)[0] = l0;
    ((__nv_bfloat162*)loP)[1] = l1;
}

struct APre { float4 p0, p1, p2, p3; };

// Double-buffered stages: [aHi TM*ALD][aLo TM*ALD][B hi+lo 2*32*NPADP] per stage.
template<int DIN, int DOUT, int NPAD, int NPADP, int OUTP, int OUT_STRIDE, int WM,
         int TM, int THREADS>
__global__ void __launch_bounds__(THREADS)
k_fkan_wmma(const float* __restrict__ in0, const float* __restrict__ in1,
            const float* __restrict__ in2,
            const float* __restrict__ lng, const float* __restrict__ lnb,
            const __nv_bfloat16* __restrict__ wp,
            float* __restrict__ out)
{
    constexpr int NCH   = DIN * 5 / 32;
    constexpr int NT    = NPAD / 16;
    constexpr int WARPS = THREADS / 32;
    constexpr int WN    = WARPS / WM;
    constexpr int MT    = (TM / 16) / WM;
    constexpr int NTW   = NT / WN;
    static_assert(WM * WN == WARPS && MT * WM * 16 == TM && NTW * WN == NT, "tiling");
    constexpr int ALD  = 40;
    constexpr int AELE = TM * ALD;
    constexpr int BELE = 2 * 32 * NPADP;
    constexpr int SELE = 2 * AELE + BELE;

    extern __shared__ char smc[];
    __nv_bfloat16* sb16 = (__nv_bfloat16*)smc;
    const uint32_t sbase = smem_u32(smc);
    float* sOut = (float*)smc;

    const int t = threadIdx.x;
    const int w = t >> 5;
    const int wm = w % WM, wn = w / WM;
    const int base = blockIdx.x * TM;

    const int r = t >> 1, half = t & 1;
    const int n = base + r;
    const bool valid = (n < NN);
    const float mu = valid ? g_mu[n] : 0.f;
    const float rs = valid ? g_rs[n] : 0.f;

    wmma::fragment<wmma::accumulator, 16, 16, 16, float> acc[MT][NTW];
    #pragma unroll
    for (int im = 0; im < MT; im++)
        #pragma unroll
        for (int in = 0; in < NTW; in++) wmma::fill_fragment(acc[im][in], 0.f);

    // ---- prefetch global loads for A chunk c into registers ----
    auto loadA = [&](int c) -> APre {
        APre P;
        P.p0 = P.p1 = P.p2 = P.p3 = make_float4(0.f, 0.f, 0.f, 0.f);
        const int kc = c * 32;
        if (kc < DIN) {
            if (valid) {
                const int c0 = kc + half * 16;
                P.p0 = ldx4<DIN>(in0, in1, in2, n, c0);
                P.p1 = ldx4<DIN>(in0, in1, in2, n, c0 + 4);
                P.p2 = ldx4<DIN>(in0, in1, in2, n, c0 + 8);
                P.p3 = ldx4<DIN>(in0, in1, in2, n, c0 + 12);
            }
        } else {
            const int xc = ((kc - DIN) >> 2) + half * 4;
            if (valid) P.p0 = ldx4<DIN>(in0, in1, in2, n, xc);
            P.p1 = *(const float4*)(lng + xc);
            P.p2 = *(const float4*)(lnb + xc);
        }
        return P;
    };
    // ---- ALU/MUFU + smem stores from prefetched registers ----
    auto computeA = [&](int c, int s, const APre& P) {
        __nv_bfloat16* aHi = sb16 + s * SELE;
        __nv_bfloat16* aLo = aHi + AELE;
        const int kc = c * 32;
        if (kc < DIN) {
            const float4 xs[4] = {P.p0, P.p1, P.p2, P.p3};
            #pragma unroll
            for (int q = 0; q < 4; q++) {
                const float4 xv = xs[q];
                float4 v;
                v.x = __fdividef(xv.x, 1.f + __expf(-xv.x));
                v.y = __fdividef(xv.y, 1.f + __expf(-xv.y));
                v.z = __fdividef(xv.z, 1.f + __expf(-xv.z));
                v.w = __fdividef(xv.w, 1.f + __expf(-xv.w));
                const int c0 = half * 16 + q * 4;
                splitstore(aHi + r * ALD + c0, aLo + r * ALD + c0, v);
            }
        } else {
            const float4 xv = P.p0, gv = P.p1, bv = P.p2;
            float zz[4];
            zz[0] = (xv.x - mu) * rs * gv.x + bv.x;
            zz[1] = (xv.y - mu) * rs * gv.y + bv.y;
            zz[2] = (xv.z - mu) * rs * gv.z + bv.z;
            zz[3] = (xv.w - mu) * rs * gv.w + bv.w;
            #pragma unroll
            for (int i = 0; i < 4; i++) {
                // rbf chain: rbf0 = exp(-9/16 (z+2)^2); ratio = exp(3z/2) with e^{2-2k}
                const float z = zz[i];
                const float zp2 = z + 2.f;
                const float r0 = __expf(-0.5625f * zp2 * zp2);
                const float B  = __expf(1.5f * z);
                float4 v;
                v.x = r0;
                v.y = r0 * B * 7.3890560989f;
                v.z = v.y * B;
                v.w = v.z * B * 0.1353352832f;
                const int c0 = half * 16 + i * 4;
                splitstore(aHi + r * ALD + c0, aLo + r * ALD + c0, v);
            }
        }
    };
    auto stageB = [&](int c, int s) {
        constexpr int NV4 = BELE * 2 / 16;
        const char* src = (const char*)(wp + (size_t)c * BELE);
        const uint32_t dst = sbase + (s * SELE + 2 * AELE) * 2;
        #pragma unroll
        for (int i = t; i < NV4; i += THREADS)
            cpasync16(dst + i * 16, src + i * 16);
    };

    // --- prologue ---
    {
        APre P0 = loadA(0);
        stageB(0, 0);
        CPCOMMIT();
        computeA(0, 0, P0);
        CPWAIT0();
        __syncthreads();
    }

    APre pre;
    for (int c = 0; c < NCH; c++) {
        const int s = c & 1;
        if (c + 1 < NCH) {
            pre = loadA(c + 1);            // gmem latency hidden under MMAs below
            stageB(c + 1, 1 - s);
            CPCOMMIT();
        }

        {
            __nv_bfloat16* aHi = sb16 + s * SELE;
            __nv_bfloat16* aLo = aHi + AELE;
            __nv_bfloat16* bHi = aLo + AELE;
            #pragma unroll
            for (int kk = 0; kk < 2; kk++) {
                wmma::fragment<wmma::matrix_a, 16, 16, 16, __nv_bfloat16, wmma::row_major> ah[MT], al[MT];
                #pragma unroll
                for (int im = 0; im < MT; im++) {
                    const int mrow = (wm * MT + im) * 16;
                    wmma::load_matrix_sync(ah[im], aHi + mrow * ALD + kk * 16, ALD);
                    wmma::load_matrix_sync(al[im], aLo + mrow * ALD + kk * 16, ALD);
                }
                #pragma unroll
                for (int in = 0; in < NTW; in++) {
                    const int col = (wn * NTW + in) * 16;
                    wmma::fragment<wmma::matrix_b, 16, 16, 16, __nv_bfloat16, wmma::row_major> bh, bl;
                    wmma::load_matrix_sync(bh, bHi + kk * 16 * NPADP + col, NPADP);
                    wmma::load_matrix_sync(bl, bHi + 32 * NPADP + kk * 16 * NPADP + col, NPADP);
                    #pragma unroll
                    for (int im = 0; im < MT; im++) {
                        wmma::mma_sync(acc[im][in], ah[im], bh, acc[im][in]);
                        wmma::mma_sync(acc[im][in], ah[im], bl, acc[im][in]);
                        wmma::mma_sync(acc[im][in], al[im], bh, acc[im][in]);
                    }
                }
            }
        }

        if (c + 1 < NCH) computeA(c + 1, 1 - s, pre);
        CPWAIT0();
        __syncthreads();
    }

    // ---- epilogue ----
    #pragma unroll
    for (int im = 0; im < MT; im++)
        #pragma unroll
        for (int in = 0; in < NTW; in++)
            wmma::store_matrix_sync(
                sOut + ((wm * MT + im) * 16) * OUTP + (wn * NTW + in) * 16,
                acc[im][in], OUTP, wmma::mem_row_major);
    __syncthreads();

    if (NPAD == 128) {
        for (int e = t; e < TM * 32; e += THREADS) {
            int rr = e >> 5, c4 = e & 31;
            int n2 = base + rr;
            if (n2 < NN)
                ((float4*)(out + (size_t)n2 * OUT_STRIDE))[c4] =
                    *(float4*)&sOut[rr * OUTP + c4 * 4];
        }
    } else {
        for (int e = t; e < TM * NPAD; e += THREADS) {
            int rr = e / NPAD, o = e % NPAD;
            int n2 = base + rr;
            if (o < DOUT && n2 < NN)
                out[(size_t)n2 * OUT_STRIDE + o] = sOut[rr * OUTP + o];
        }
    }
}

// ---------------- aggregation + fused layernorm stats ----------------
__global__ void k_agg128(const float* __restrict__ tin, float* __restrict__ outp,
                         const float* __restrict__ bs, const float* __restrict__ bb,
                         const float* __restrict__ bg, int statmode) {
    int gw = (blockIdx.x * blockDim.x + threadIdx.x) >> 5;
    int lane = threadIdx.x & 31;
    if (gw >= NN) return;
    int beg = g_rowp[gw], end = g_rowp[gw + 1];
    const float4* t4 = (const float4*)tin;
    float4 a = make_float4(0.f, 0.f, 0.f, 0.f);
    float sw = 0.f;
    int j = beg;
    for (; j + 1 < end; j += 2) {
        int s0 = g_esrc[j], s1 = g_esrc[j + 1];
        float w0 = g_dinv[s0], w1 = g_dinv[s1];
        sw += w0 + w1;
        float4 v0 = t4[(size_t)s0 * 32 + lane];
        float4 v1 = t4[(size_t)s1 * 32 + lane];
        a.x += w0 * v0.x + w1 * v1.x;
        a.y += w0 * v0.y + w1 * v1.y;
        a.z += w0 * v0.z + w1 * v1.z;
        a.w += w0 * v0.w + w1 * v1.w;
    }
    if (j < end) {
        int s0 = g_esrc[j];
        float w0 = g_dinv[s0];
        sw += w0;
        float4 v0 = t4[(size_t)s0 * 32 + lane];
        a.x += w0 * v0.x; a.y += w0 * v0.y; a.z += w0 * v0.z; a.w += w0 * v0.w;
    }
    float dn = g_dinv[gw];
    float wb = dn * (sw + dn);
    float4 sv = t4[(size_t)gw * 32 + lane];
    float4 bgv = ((const float4*)bg)[lane];
    float4 bsv = ((const float4*)bs)[lane];
    float4 bbv = ((const float4*)bb)[lane];
    float4 o;
    o.x = dn * (a.x + dn * sv.x) + (bsv.x + bbv.x) * wb + bgv.x;
    o.y = dn * (a.y + dn * sv.y) + (bsv.y + bbv.y) * wb + bgv.y;
    o.z = dn * (a.z + dn * sv.z) + (bsv.z + bbv.z) * wb + bgv.z;
    o.w = dn * (a.w + dn * sv.w) + (bsv.w + bbv.w) * wb + bgv.w;
    ((float4*)outp)[(size_t)gw * 32 + lane] = o;

    float s  = o.x + o.y + o.z + o.w;
    float s2 = o.x * o.x + o.y * o.y + o.z * o.z + o.w * o.w;
    #pragma unroll
    for (int d = 16; d; d >>= 1) {
        s  += __shfl_xor_sync(0xffffffffu, s,  d);
        s2 += __shfl_xor_sync(0xffffffffu, s2, d);
    }
    if (lane == 0) {
        if (statmode == 1) {
            float m = s * (1.f / 128.f);
            g_mu[gw] = m;
            g_rs[gw] = rsqrtf(s2 * (1.f / 128.f) - m * m + 1e-5f);
            g_sA[gw]  += s;
            g_sA2[gw] += s2;
        } else {
            float ts  = g_sA[gw]  + s;
            float ts2 = g_sA2[gw] + s2;
            float m = ts * (1.f / 384.f);
            g_mu[gw] = m;
            g_rs[gw] = rsqrtf(ts2 * (1.f / 384.f) - m * m + 1e-5f);
        }
    }
}

__global__ void k_agg47(const float* __restrict__ tin, float* __restrict__ outp,
                        const float* __restrict__ bs, const float* __restrict__ bb,
                        const float* __restrict__ bg) {
    int gw = (blockIdx.x * blockDim.x + threadIdx.x) >> 5;
    int lane = threadIdx.x & 31;
    if (gw >= NN) return;
    int beg = g_rowp[gw], end = g_rowp[gw + 1];
    float a0 = 0.f, a1 = 0.f, sw = 0.f;
    for (int j = beg; j < end; j++) {
        int s = g_esrc[j];
        float w = g_dinv[s];
        sw += w;
        const float* ts = tin + (size_t)s * 64;
        a0 += w * ts[lane];
        if (lane < 15) a1 += w * ts[32 + lane];
    }
    float dn = g_dinv[gw];
    float wb = dn * (sw + dn);
    const float* tn = tin + (size_t)gw * 64;
    outp[(size_t)gw * 47 + lane] =
        dn * (a0 + dn * tn[lane]) + (bs[lane] + bb[lane]) * wb + bg[lane];
    if (lane < 15)
        outp[(size_t)gw * 47 + 32 + lane] =
            dn * (a1 + dn * tn[32 + lane]) + (bs[32 + lane] + bb[32 + lane]) * wb + bg[32 + lane];
}

// ---------------- driver ----------------
extern "C" void kernel_launch(void* const* d_in, const int* in_sizes, int n_in,
                              void* d_out, int out_size) {
    const float* x    = (const float*)d_in[0];
    const int*   ei   = (const int*)d_in[1];
    const float* lng0 = (const float*)d_in[2];
    const float* lnb0 = (const float*)d_in[3];
    const float* Ws0  = (const float*)d_in[4];
    const float* bs0  = (const float*)d_in[5];
    const float* Wb0  = (const float*)d_in[6];
    const float* bb0  = (const float*)d_in[7];
    const float* bg0  = (const float*)d_in[8];
    const float* lng1 = (const float*)d_in[9];
    const float* lnb1 = (const float*)d_in[10];
    const float* Ws1  = (const float*)d_in[11];
    const float* bs1  = (const float*)d_in[12];
    const float* Wb1  = (const float*)d_in[13];
    const float* bb1  = (const float*)d_in[14];
    const float* bg1  = (const float*)d_in[15];
    const float* lng2 = (const float*)d_in[16];
    const float* lnb2 = (const float*)d_in[17];
    const float* Ws2  = (const float*)d_in[18];
    const float* bs2  = (const float*)d_in[19];
    const float* Wb2  = (const float*)d_in[20];
    const float* bb2  = (const float*)d_in[21];
    const float* bg2  = (const float*)d_in[22];
    float* outp = (float*)d_out;

    void *pt, *ph1, *ph2, *pt2, *pw0, *pw1, *pw2;
    cudaGetSymbolAddress(&pt,  g_t);
    cudaGetSymbolAddress(&ph1, g_h1);
    cudaGetSymbolAddress(&ph2, g_h2);
    cudaGetSymbolAddress(&pt2, g_t2);
    cudaGetSymbolAddress(&pw0, g_wb0);
    cudaGetSymbolAddress(&pw1, g_wb1);
    cudaGetSymbolAddress(&pw2, g_wb2);

    const int STG_L01 = 2 * (2 * 256 * 40 + 2 * 32 * 136) * 2;   // 116736
    const int EPI_L01 = 256 * 132 * 4;                            // 135168
    const int SM_L01  = EPI_L01 > STG_L01 ? EPI_L01 : STG_L01;
    const int STG_L2  = 2 * (2 * 256 * 40 + 2 * 32 * 56) * 2;    // 96256
    const int EPI_L2  = 256 * 52 * 4;
    const int SM_L2   = STG_L2 > EPI_L2 ? STG_L2 : EPI_L2;
    cudaFuncSetAttribute(
        (const void*)k_fkan_wmma<128, 128, 128, 136, 132, 128, 8, 256, 512>,
        cudaFuncAttributeMaxDynamicSharedMemorySize, SM_L01);
    cudaFuncSetAttribute(
        (const void*)k_fkan_wmma<384, 47, 48, 56, 52, 64, 16, 256, 512>,
        cudaFuncAttributeMaxDynamicSharedMemorySize, SM_L2);

    const int FG = (NN + 255) / 256;          // 391
    const int SG = (NN * 32 + 255) / 256;     // warp per node

    // launches 1-3 (ncu profiles launch #4 -> make it fkan layer-0)
    k_statx<<<SG, 256>>>(x);
    k_prepw<128, 128, 128, 136><<<(20 * 2 * 32 * 136 + 255) / 256, 256>>>(
        Wb0, Ws0, (__nv_bfloat16*)pw0);
    k_zero_deg<<<(NN + 255) / 256, 256>>>();

    // launch #4: layer-0 fkan (PROFILED)
    k_fkan_wmma<128, 128, 128, 136, 132, 128, 8, 256, 512><<<FG, 512, SM_L01>>>(
        x, nullptr, nullptr, lng0, lnb0, (const __nv_bfloat16*)pw0, (float*)pt);

    // remaining prep (independent of layer-0 output)
    k_prepw<128, 128, 128, 136><<<(20 * 2 * 32 * 136 + 255) / 256, 256>>>(
        Wb1, Ws1, (__nv_bfloat16*)pw1);
    k_prepw<384, 47, 48, 56><<<(60 * 2 * 32 * 56 + 255) / 256, 256>>>(
        Wb2, Ws2, (__nv_bfloat16*)pw2);
    k_count<<<(EE + 255) / 256, 256>>>(ei);
    k_scan<<<1, 1024>>>();
    k_dinv<<<(NN + 255) / 256, 256>>>();
    k_place<<<(EE + 255) / 256, 256>>>(ei);

    k_agg128<<<SG, 256>>>((const float*)pt, (float*)ph1, bs0, bb0, bg0, 1);

    // layer 1
    k_fkan_wmma<128, 128, 128, 136, 132, 128, 8, 256, 512><<<FG, 512, SM_L01>>>(
        (const float*)ph1, nullptr, nullptr, lng1, lnb1, (const __nv_bfloat16*)pw1,
        (float*)pt);
    k_agg128<<<SG, 256>>>((const float*)pt, (float*)ph2, bs1, bb1, bg1, 2);

    // layer 2
    k_fkan_wmma<384, 47, 48, 56, 52, 64, 16, 256, 512><<<FG, 512, SM_L2>>>(
        x, (const float*)ph1, (const float*)ph2, lng2, lnb2,
        (const __nv_bfloat16*)pw2, (float*)pt2);
    k_agg47<<<SG, 256>>>((const float*)pt2, outp, bs2, bb2, bg2);
}

// round 10
// speedup vs baseline: 1.0673x; 1.0673x over previous
#include <cuda_runtime.h>
#include <cuda_bf16.h>
#include <mma.h>
#include <cstdint>
#include <math.h>

using namespace nvcuda;

#define NN 100000
#define NN2 100352   // padded row count (multiple of 256) for unguarded tile stores
#define EE 1600000

// ---------------- scratch (device globals; no runtime allocation) ----------------
__device__ int   g_deg[NN];
__device__ int   g_rowp[NN + 1];
__device__ int   g_cur[NN];
__device__ int   g_esrc[EE];
__device__ float g_dinv[NN];
__device__ float g_mu[NN];
__device__ float g_rs[NN];
__device__ float g_sA[NN];
__device__ float g_sA2[NN];
__device__ float g_t [NN2 * 128];
__device__ float g_h1[NN2 * 128];
__device__ float g_h2[NN2 * 128];
__device__ float g_t2[NN2 * 64];
// packed bf16-split weights: per chunk [hi 32*NPADP][lo 32*NPADP]
__device__ __align__(16) __nv_bfloat16 g_wb0[20 * 2 * 32 * 136];
__device__ __align__(16) __nv_bfloat16 g_wb1[20 * 2 * 32 * 136];
__device__ __align__(16) __nv_bfloat16 g_wb2[60 * 2 * 32 * 56];

// ---------------- async-copy helpers ----------------
__device__ __forceinline__ uint32_t smem_u32(const void* p) {
    uint32_t a;
    asm("{ .reg .u64 t; cvta.to.shared.u64 t, %1; cvt.u32.u64 %0, t; }"
        : "=r"(a) : "l"(p));
    return a;
}
__device__ __forceinline__ void cpasync16(uint32_t dst, const void* src) {
    asm volatile("cp.async.cg.shared.global [%0], [%1], 16;" :: "r"(dst), "l"(src));
}
#define CPCOMMIT() asm volatile("cp.async.commit_group;" ::: "memory")
#define CPWAIT0()  asm volatile("cp.async.wait_group 0;" ::: "memory")

// ---------------- graph preprocessing ----------------
__global__ void k_zero_deg() {
    int i = blockIdx.x * blockDim.x + threadIdx.x;
    if (i < NN) g_deg[i] = 0;
}
__global__ void k_count(const int* __restrict__ ei) {
    int e = blockIdx.x * blockDim.x + threadIdx.x;
    if (e < EE) atomicAdd(&g_deg[ei[EE + e]], 1);
}
__global__ void k_scan() {
    __shared__ int wsum[32];
    __shared__ int scarry;
    int t = threadIdx.x, lane = t & 31, wid = t >> 5;
    if (t == 0) scarry = 0;
    __syncthreads();
    for (int base = 0; base < NN; base += 1024) {
        int i = base + t;
        int v = (i < NN) ? g_deg[i] : 0;
        int x = v;
        #pragma unroll
        for (int d = 1; d < 32; d <<= 1) {
            int y = __shfl_up_sync(0xffffffffu, x, d);
            if (lane >= d) x += y;
        }
        if (lane == 31) wsum[wid] = x;
        __syncthreads();
        if (wid == 0) {
            int ws = wsum[lane];
            #pragma unroll
            for (int d = 1; d < 32; d <<= 1) {
                int y = __shfl_up_sync(0xffffffffu, ws, d);
                if (lane >= d) ws += y;
            }
            wsum[lane] = ws;
        }
        __syncthreads();
        int carry = scarry;
        int excl = carry + (wid ? wsum[wid - 1] : 0) + (x - v);
        if (i < NN) { g_rowp[i] = excl; g_cur[i] = excl; }
        __syncthreads();
        if (t == 0) scarry = carry + wsum[31];
        __syncthreads();
    }
    if (t == 0) g_rowp[NN] = scarry;
}
__global__ void k_dinv() {
    int i = blockIdx.x * blockDim.x + threadIdx.x;
    if (i < NN) g_dinv[i] = rsqrtf((float)(g_deg[i] + 1));
}
__global__ void k_place(const int* __restrict__ ei) {
    int e = blockIdx.x * blockDim.x + threadIdx.x;
    if (e < EE) {
        int d = ei[EE + e];
        int pos = atomicAdd(&g_cur[d], 1);
        g_esrc[pos] = ei[e];
    }
}

// ---------------- weight precompute: bf16 hi/lo, chunk-packed ----------------
template<int DIN, int DOUT, int NPAD, int NPADP>
__global__ void k_prepw(const float* __restrict__ Wb, const float* __restrict__ Ws,
                        __nv_bfloat16* __restrict__ dst) {
    constexpr int NCH = DIN * 5 / 32;
    int idx = blockIdx.x * blockDim.x + threadIdx.x;
    if (idx >= NCH * 2 * 32 * NPADP) return;
    int n = idx % NPADP;
    int k = (idx / NPADP) & 31;
    int h = (idx / (NPADP * 32)) & 1;
    int c = idx / (NPADP * 32 * 2);
    int kg = c * 32 + k;
    float w = 0.f;
    if (n < DOUT) {
        if (kg < DIN) w = Wb[(size_t)n * DIN + kg];
        else          w = Ws[(size_t)n * (DIN * 4) + (kg - DIN)];
    }
    __nv_bfloat16 hi = __float2bfloat16(w);
    __nv_bfloat16 lo = __float2bfloat16(w - __bfloat162float(hi));
    dst[idx] = h ? lo : hi;
}

// ---------------- stats of x (warp per node): mu0/rs0 + partials ----------------
__global__ void k_statx(const float* __restrict__ x) {
    int gw = (blockIdx.x * blockDim.x + threadIdx.x) >> 5;
    int lane = threadIdx.x & 31;
    if (gw >= NN) return;
    float4 v = ((const float4*)(x + (size_t)gw * 128))[lane];
    float s  = v.x + v.y + v.z + v.w;
    float s2 = v.x * v.x + v.y * v.y + v.z * v.z + v.w * v.w;
    #pragma unroll
    for (int d = 16; d; d >>= 1) {
        s  += __shfl_xor_sync(0xffffffffu, s,  d);
        s2 += __shfl_xor_sync(0xffffffffu, s2, d);
    }
    if (lane == 0) {
        float m = s * (1.f / 128.f);
        g_mu[gw] = m;
        g_rs[gw] = rsqrtf(s2 * (1.f / 128.f) - m * m + 1e-5f);
        g_sA[gw]  = s;
        g_sA2[gw] = s2;
    }
}

// ---------------- fused FastKAN layer via wmma bf16 (3-term compensation) ----------------
template<int DIN>
__device__ __forceinline__ float4 ldx4(const float* __restrict__ a,
                                       const float* __restrict__ b,
                                       const float* __restrict__ c,
                                       int n, int col) {
    if (DIN == 128) return *(const float4*)(a + (size_t)n * 128 + col);
    const float* p = (col < 128) ? a : (col < 256) ? b : c;
    return *(const float4*)(p + (size_t)n * 128 + (col & 127));
}

__device__ __forceinline__ void splitstore(__nv_bfloat16* hiP, __nv_bfloat16* loP,
                                           float4 v) {
    __nv_bfloat162 h0 = __floats2bfloat162_rn(v.x, v.y);
    __nv_bfloat162 h1 = __floats2bfloat162_rn(v.z, v.w);
    float2 f0 = __bfloat1622float2(h0);
    float2 f1 = __bfloat1622float2(h1);
    __nv_bfloat162 l0 = __floats2bfloat162_rn(v.x - f0.x, v.y - f0.y);
    __nv_bfloat162 l1 = __floats2bfloat162_rn(v.z - f1.x, v.w - f1.y);
    ((__nv_bfloat162*)hiP)[0] = h0;
    ((__nv_bfloat162*)hiP)[1] = h1;
    ((__nv_bfloat162*)loP)[0] = l0;
    ((__nv_bfloat162*)loP)[1] = l1;
}

// Double-buffered stages: [aHi TM*ALD][aLo TM*ALD][B hi+lo 2*32*NPADP] per stage.
// Epilogue stores fragments directly to gmem (out buffers padded to NN2 rows).
template<int DIN, int DOUT, int NPAD, int NPADP, int OUT_STRIDE, int WM,
         int TM, int THREADS>
__global__ void __launch_bounds__(THREADS, 512 / THREADS)
k_fkan_wmma(const float* __restrict__ in0, const float* __restrict__ in1,
            const float* __restrict__ in2,
            const float* __restrict__ lng, const float* __restrict__ lnb,
            const __nv_bfloat16* __restrict__ wp,
            float* __restrict__ out)
{
    constexpr int NCH   = DIN * 5 / 32;
    constexpr int NT    = NPAD / 16;
    constexpr int WARPS = THREADS / 32;
    constexpr int WN    = WARPS / WM;
    constexpr int MT    = (TM / 16) / WM;
    constexpr int NTW   = NT / WN;
    static_assert(WM * WN == WARPS && MT * WM * 16 == TM && NTW * WN == NT, "tiling");
    constexpr int ALD  = 40;
    constexpr int AELE = TM * ALD;
    constexpr int BELE = 2 * 32 * NPADP;
    constexpr int SELE = 2 * AELE + BELE;

    extern __shared__ char smc[];
    __nv_bfloat16* sb16 = (__nv_bfloat16*)smc;
    const uint32_t sbase = smem_u32(smc);

    const int t = threadIdx.x;
    const int w = t >> 5;
    const int wm = w % WM, wn = w / WM;
    const int base = blockIdx.x * TM;

    const int r = t >> 1, half = t & 1;
    const int n = base + r;
    const bool valid = (n < NN);
    const float mu = valid ? g_mu[n] : 0.f;
    const float rs = valid ? g_rs[n] : 0.f;

    wmma::fragment<wmma::accumulator, 16, 16, 16, float> acc[MT][NTW];
    #pragma unroll
    for (int im = 0; im < MT; im++)
        #pragma unroll
        for (int in = 0; in < NTW; in++) wmma::fill_fragment(acc[im][in], 0.f);

    auto stageA = [&](int c, int s) {
        __nv_bfloat16* aHi = sb16 + s * SELE;
        __nv_bfloat16* aLo = aHi + AELE;
        const int kc = c * 32;
        if (kc < DIN) {
            #pragma unroll
            for (int q = 0; q < 4; q++) {
                const int c0 = half * 16 + q * 4;
                float4 xv = make_float4(0.f, 0.f, 0.f, 0.f);
                if (valid) xv = ldx4<DIN>(in0, in1, in2, n, kc + c0);
                float4 v;
                v.x = __fdividef(xv.x, 1.f + __expf(-xv.x));
                v.y = __fdividef(xv.y, 1.f + __expf(-xv.y));
                v.z = __fdividef(xv.z, 1.f + __expf(-xv.z));
                v.w = __fdividef(xv.w, 1.f + __expf(-xv.w));
                splitstore(aHi + r * ALD + c0, aLo + r * ALD + c0, v);
            }
        } else {
            const int xc = ((kc - DIN) >> 2) + half * 4;
            float4 xv = make_float4(0.f, 0.f, 0.f, 0.f);
            if (valid) xv = ldx4<DIN>(in0, in1, in2, n, xc);
            const float4 gv = *(const float4*)(lng + xc);
            const float4 bv = *(const float4*)(lnb + xc);
            float zz[4];
            zz[0] = (xv.x - mu) * rs * gv.x + bv.x;
            zz[1] = (xv.y - mu) * rs * gv.y + bv.y;
            zz[2] = (xv.z - mu) * rs * gv.z + bv.z;
            zz[3] = (xv.w - mu) * rs * gv.w + bv.w;
            #pragma unroll
            for (int i = 0; i < 4; i++) {
                // rbf chain: rbf0 = exp(-9/16 (z+2)^2); ratio = exp(3z/2) with e^{2-2k}
                const float z = zz[i];
                const float zp2 = z + 2.f;
                const float r0 = __expf(-0.5625f * zp2 * zp2);
                const float B  = __expf(1.5f * z);
                float4 v;
                v.x = r0;
                v.y = r0 * B * 7.3890560989f;
                v.z = v.y * B;
                v.w = v.z * B * 0.1353352832f;
                const int c0 = half * 16 + i * 4;
                splitstore(aHi + r * ALD + c0, aLo + r * ALD + c0, v);
            }
        }
    };
    auto stageB = [&](int c, int s) {
        constexpr int NV4 = BELE * 2 / 16;
        const char* src = (const char*)(wp + (size_t)c * BELE);
        const uint32_t dst = sbase + (s * SELE + 2 * AELE) * 2;
        #pragma unroll
        for (int i = t; i < NV4; i += THREADS)
            cpasync16(dst + i * 16, src + i * 16);
    };

    // --- prologue ---
    stageB(0, 0);
    CPCOMMIT();
    stageA(0, 0);
    CPWAIT0();
    __syncthreads();

    for (int c = 0; c < NCH; c++) {
        const int s = c & 1;
        if (c + 1 < NCH) { stageB(c + 1, 1 - s); CPCOMMIT(); }

        {
            __nv_bfloat16* aHi = sb16 + s * SELE;
            __nv_bfloat16* aLo = aHi + AELE;
            __nv_bfloat16* bHi = aLo + AELE;
            #pragma unroll
            for (int kk = 0; kk < 2; kk++) {
                wmma::fragment<wmma::matrix_a, 16, 16, 16, __nv_bfloat16, wmma::row_major> ah[MT], al[MT];
                #pragma unroll
                for (int im = 0; im < MT; im++) {
                    const int mrow = (wm * MT + im) * 16;
                    wmma::load_matrix_sync(ah[im], aHi + mrow * ALD + kk * 16, ALD);
                    wmma::load_matrix_sync(al[im], aLo + mrow * ALD + kk * 16, ALD);
                }
                #pragma unroll
                for (int in = 0; in < NTW; in++) {
                    const int col = (wn * NTW + in) * 16;
                    wmma::fragment<wmma::matrix_b, 16, 16, 16, __nv_bfloat16, wmma::row_major> bh, bl;
                    wmma::load_matrix_sync(bh, bHi + kk * 16 * NPADP + col, NPADP);
                    wmma::load_matrix_sync(bl, bHi + 32 * NPADP + kk * 16 * NPADP + col, NPADP);
                    #pragma unroll
                    for (int im = 0; im < MT; im++) {
                        wmma::mma_sync(acc[im][in], ah[im], bh, acc[im][in]);
                        wmma::mma_sync(acc[im][in], ah[im], bl, acc[im][in]);
                        wmma::mma_sync(acc[im][in], al[im], bh, acc[im][in]);
                    }
                }
            }
        }

        if (c + 1 < NCH) stageA(c + 1, 1 - s);
        CPWAIT0();
        __syncthreads();
    }

    // ---- epilogue: fragments straight to gmem (out buffers padded to NN2 rows) ----
    #pragma unroll
    for (int im = 0; im < MT; im++)
        #pragma unroll
        for (int in = 0; in < NTW; in++) {
            const int mrow = (wm * MT + im) * 16;
            const int col  = (wn * NTW + in) * 16;
            wmma::store_matrix_sync(out + (size_t)(base + mrow) * OUT_STRIDE + col,
                                    acc[im][in], OUT_STRIDE, wmma::mem_row_major);
        }
}

// ---------------- aggregation + fused layernorm stats ----------------
__global__ void k_agg128(const float* __restrict__ tin, float* __restrict__ outp,
                         const float* __restrict__ bs, const float* __restrict__ bb,
                         const float* __restrict__ bg, int statmode) {
    int gw = (blockIdx.x * blockDim.x + threadIdx.x) >> 5;
    int lane = threadIdx.x & 31;
    if (gw >= NN) return;
    int beg = g_rowp[gw], end = g_rowp[gw + 1];
    const float4* t4 = (const float4*)tin;
    float4 a = make_float4(0.f, 0.f, 0.f, 0.f);
    float sw = 0.f;
    int j = beg;
    for (; j + 1 < end; j += 2) {
        int s0 = g_esrc[j], s1 = g_esrc[j + 1];
        float w0 = g_dinv[s0], w1 = g_dinv[s1];
        sw += w0 + w1;
        float4 v0 = t4[(size_t)s0 * 32 + lane];
        float4 v1 = t4[(size_t)s1 * 32 + lane];
        a.x += w0 * v0.x + w1 * v1.x;
        a.y += w0 * v0.y + w1 * v1.y;
        a.z += w0 * v0.z + w1 * v1.z;
        a.w += w0 * v0.w + w1 * v1.w;
    }
    if (j < end) {
        int s0 = g_esrc[j];
        float w0 = g_dinv[s0];
        sw += w0;
        float4 v0 = t4[(size_t)s0 * 32 + lane];
        a.x += w0 * v0.x; a.y += w0 * v0.y; a.z += w0 * v0.z; a.w += w0 * v0.w;
    }
    float dn = g_dinv[gw];
    float wb = dn * (sw + dn);
    float4 sv = t4[(size_t)gw * 32 + lane];
    float4 bgv = ((const float4*)bg)[lane];
    float4 bsv = ((const float4*)bs)[lane];
    float4 bbv = ((const float4*)bb)[lane];
    float4 o;
    o.x = dn * (a.x + dn * sv.x) + (bsv.x + bbv.x) * wb + bgv.x;
    o.y = dn * (a.y + dn * sv.y) + (bsv.y + bbv.y) * wb + bgv.y;
    o.z = dn * (a.z + dn * sv.z) + (bsv.z + bbv.z) * wb + bgv.z;
    o.w = dn * (a.w + dn * sv.w) + (bsv.w + bbv.w) * wb + bgv.w;
    ((float4*)outp)[(size_t)gw * 32 + lane] = o;

    float s  = o.x + o.y + o.z + o.w;
    float s2 = o.x * o.x + o.y * o.y + o.z * o.z + o.w * o.w;
    #pragma unroll
    for (int d = 16; d; d >>= 1) {
        s  += __shfl_xor_sync(0xffffffffu, s,  d);
        s2 += __shfl_xor_sync(0xffffffffu, s2, d);
    }
    if (lane == 0) {
        if (statmode == 1) {
            float m = s * (1.f / 128.f);
            g_mu[gw] = m;
            g_rs[gw] = rsqrtf(s2 * (1.f / 128.f) - m * m + 1e-5f);
            g_sA[gw]  += s;
            g_sA2[gw] += s2;
        } else {
            float ts  = g_sA[gw]  + s;
            float ts2 = g_sA2[gw] + s2;
            float m = ts * (1.f / 384.f);
            g_mu[gw] = m;
            g_rs[gw] = rsqrtf(ts2 * (1.f / 384.f) - m * m + 1e-5f);
        }
    }
}

__global__ void k_agg47(const float* __restrict__ tin, float* __restrict__ outp,
                        const float* __restrict__ bs, const float* __restrict__ bb,
                        const float* __restrict__ bg) {
    int gw = (blockIdx.x * blockDim.x + threadIdx.x) >> 5;
    int lane = threadIdx.x & 31;
    if (gw >= NN) return;
    int beg = g_rowp[gw], end = g_rowp[gw + 1];
    float a0 = 0.f, a1 = 0.f, sw = 0.f;
    for (int j = beg; j < end; j++) {
        int s = g_esrc[j];
        float w = g_dinv[s];
        sw += w;
        const float* ts = tin + (size_t)s * 64;
        a0 += w * ts[lane];
        if (lane < 15) a1 += w * ts[32 + lane];
    }
    float dn = g_dinv[gw];
    float wb = dn * (sw + dn);
    const float* tn = tin + (size_t)gw * 64;
    outp[(size_t)gw * 47 + lane] =
        dn * (a0 + dn * tn[lane]) + (bs[lane] + bb[lane]) * wb + bg[lane];
    if (lane < 15)
        outp[(size_t)gw * 47 + 32 + lane] =
            dn * (a1 + dn * tn[32 + lane]) + (bs[32 + lane] + bb[32 + lane]) * wb + bg[32 + lane];
}

// ---------------- driver ----------------
extern "C" void kernel_launch(void* const* d_in, const int* in_sizes, int n_in,
                              void* d_out, int out_size) {
    const float* x    = (const float*)d_in[0];
    const int*   ei   = (const int*)d_in[1];
    const float* lng0 = (const float*)d_in[2];
    const float* lnb0 = (const float*)d_in[3];
    const float* Ws0  = (const float*)d_in[4];
    const float* bs0  = (const float*)d_in[5];
    const float* Wb0  = (const float*)d_in[6];
    const float* bb0  = (const float*)d_in[7];
    const float* bg0  = (const float*)d_in[8];
    const float* lng1 = (const float*)d_in[9];
    const float* lnb1 = (const float*)d_in[10];
    const float* Ws1  = (const float*)d_in[11];
    const float* bs1  = (const float*)d_in[12];
    const float* Wb1  = (const float*)d_in[13];
    const float* bb1  = (const float*)d_in[14];
    const float* bg1  = (const float*)d_in[15];
    const float* lng2 = (const float*)d_in[16];
    const float* lnb2 = (const float*)d_in[17];
    const float* Ws2  = (const float*)d_in[18];
    const float* bs2  = (const float*)d_in[19];
    const float* Wb2  = (const float*)d_in[20];
    const float* bb2  = (const float*)d_in[21];
    const float* bg2  = (const float*)d_in[22];
    float* outp = (float*)d_out;

    void *pt, *ph1, *ph2, *pt2, *pw0, *pw1, *pw2;
    cudaGetSymbolAddress(&pt,  g_t);
    cudaGetSymbolAddress(&ph1, g_h1);
    cudaGetSymbolAddress(&ph2, g_h2);
    cudaGetSymbolAddress(&pt2, g_t2);
    cudaGetSymbolAddress(&pw0, g_wb0);
    cudaGetSymbolAddress(&pw1, g_wb1);
    cudaGetSymbolAddress(&pw2, g_wb2);

    // staging-only smem now (direct-gmem epilogue)
    const int SM_L01 = 2 * (2 * 128 * 40 + 2 * 32 * 136) * 2;   // 75776 (2 CTAs/SM)
    const int SM_L2  = 2 * (2 * 256 * 40 + 2 * 32 * 56) * 2;    // 96256 (1 CTA/SM)
    cudaFuncSetAttribute(
        (const void*)k_fkan_wmma<128, 128, 128, 136, 128, 4, 128, 256>,
        cudaFuncAttributeMaxDynamicSharedMemorySize, SM_L01);
    cudaFuncSetAttribute(
        (const void*)k_fkan_wmma<384, 47, 48, 56, 64, 16, 256, 512>,
        cudaFuncAttributeMaxDynamicSharedMemorySize, SM_L2);

    const int FG01 = (NN + 127) / 128;        // 782
    const int FG2  = (NN + 255) / 256;        // 391
    const int SG   = (NN * 32 + 255) / 256;   // warp per node

    // launches 1-3 (ncu profiles launch #4 -> keep it fkan layer-0)
    k_statx<<<SG, 256>>>(x);
    k_prepw<128, 128, 128, 136><<<(20 * 2 * 32 * 136 + 255) / 256, 256>>>(
        Wb0, Ws0, (__nv_bfloat16*)pw0);
    k_zero_deg<<<(NN + 255) / 256, 256>>>();

    // launch #4: layer-0 fkan (PROFILED)
    k_fkan_wmma<128, 128, 128, 136, 128, 4, 128, 256><<<FG01, 256, SM_L01>>>(
        x, nullptr, nullptr, lng0, lnb0, (const __nv_bfloat16*)pw0, (float*)pt);

    // remaining prep (independent of layer-0 output)
    k_prepw<128, 128, 128, 136><<<(20 * 2 * 32 * 136 + 255) / 256, 256>>>(
        Wb1, Ws1, (__nv_bfloat16*)pw1);
    k_prepw<384, 47, 48, 56><<<(60 * 2 * 32 * 56 + 255) / 256, 256>>>(
        Wb2, Ws2, (__nv_bfloat16*)pw2);
    k_count<<<(EE + 255) / 256, 256>>>(ei);
    k_scan<<<1, 1024>>>();
    k_dinv<<<(NN + 255) / 256, 256>>>();
    k_place<<<(EE + 255) / 256, 256>>>(ei);

    k_agg128<<<SG, 256>>>((const float*)pt, (float*)ph1, bs0, bb0, bg0, 1);

    // layer 1
    k_fkan_wmma<128, 128, 128, 136, 128, 4, 128, 256><<<FG01, 256, SM_L01>>>(
        (const float*)ph1, nullptr, nullptr, lng1, lnb1, (const __nv_bfloat16*)pw1,
        (float*)pt);
    k_agg128<<<SG, 256>>>((const float*)pt, (float*)ph2, bs1, bb1, bg1, 2);

    // layer 2
    k_fkan_wmma<384, 47, 48, 56, 64, 16, 256, 512><<<FG2, 512, SM_L2>>>(
        x, (const float*)ph1, (const float*)ph2, lng2, lnb2,
        (const __nv_bfloat16*)pw2, (float*)pt2);
    k_agg47<<<SG, 256>>>((const float*)pt2, outp, bs2, bb2, bg2);
}

// round 11
// speedup vs baseline: 1.0829x; 1.0147x over previous
#include <cuda_runtime.h>
#include <cuda_bf16.h>
#include <mma.h>
#include <cstdint>
#include <math.h>

using namespace nvcuda;

#define NN 100000
#define NN2 100352   // padded row count (multiple of 256) for unguarded tile stores
#define EE 1600000

// ---------------- scratch (device globals; no runtime allocation) ----------------
__device__ int   g_deg[NN];
__device__ int   g_rowp[NN + 1];
__device__ int   g_cur[NN];
__device__ int   g_esrc[EE];
__device__ float g_dinv[NN];
__device__ float g_mu[NN];
__device__ float g_rs[NN];
__device__ float g_sA[NN];
__device__ float g_sA2[NN];
__device__ float g_t [NN2 * 128];
__device__ float g_h1[NN2 * 128];
__device__ float g_h2[NN2 * 128];
__device__ float g_t2[NN2 * 64];
// packed bf16-split weights: per chunk [hi 32*NPADP][lo 32*NPADP]
__device__ __align__(16) __nv_bfloat16 g_wb0[20 * 2 * 32 * 136];
__device__ __align__(16) __nv_bfloat16 g_wb1[20 * 2 * 32 * 136];
__device__ __align__(16) __nv_bfloat16 g_wb2[60 * 2 * 32 * 56];

// ---------------- async-copy helpers ----------------
__device__ __forceinline__ uint32_t smem_u32(const void* p) {
    uint32_t a;
    asm("{ .reg .u64 t; cvta.to.shared.u64 t, %1; cvt.u32.u64 %0, t; }"
        : "=r"(a) : "l"(p));
    return a;
}
__device__ __forceinline__ void cpasync16(uint32_t dst, const void* src) {
    asm volatile("cp.async.cg.shared.global [%0], [%1], 16;" :: "r"(dst), "l"(src));
}
#define CPCOMMIT() asm volatile("cp.async.commit_group;" ::: "memory")
#define CPWAIT0()  asm volatile("cp.async.wait_group 0;" ::: "memory")

// ---------------- graph preprocessing ----------------
__global__ void k_zero_deg() {
    int i = blockIdx.x * blockDim.x + threadIdx.x;
    if (i < NN) g_deg[i] = 0;
}
__global__ void k_count(const int* __restrict__ ei) {
    int e = blockIdx.x * blockDim.x + threadIdx.x;
    if (e < EE) atomicAdd(&g_deg[ei[EE + e]], 1);
}
__global__ void k_scan() {
    __shared__ int wsum[32];
    __shared__ int scarry;
    int t = threadIdx.x, lane = t & 31, wid = t >> 5;
    if (t == 0) scarry = 0;
    __syncthreads();
    for (int base = 0; base < NN; base += 1024) {
        int i = base + t;
        int v = (i < NN) ? g_deg[i] : 0;
        int x = v;
        #pragma unroll
        for (int d = 1; d < 32; d <<= 1) {
            int y = __shfl_up_sync(0xffffffffu, x, d);
            if (lane >= d) x += y;
        }
        if (lane == 31) wsum[wid] = x;
        __syncthreads();
        if (wid == 0) {
            int ws = wsum[lane];
            #pragma unroll
            for (int d = 1; d < 32; d <<= 1) {
                int y = __shfl_up_sync(0xffffffffu, ws, d);
                if (lane >= d) ws += y;
            }
            wsum[lane] = ws;
        }
        __syncthreads();
        int carry = scarry;
        int excl = carry + (wid ? wsum[wid - 1] : 0) + (x - v);
        if (i < NN) { g_rowp[i] = excl; g_cur[i] = excl; }
        __syncthreads();
        if (t == 0) scarry = carry + wsum[31];
        __syncthreads();
    }
    if (t == 0) g_rowp[NN] = scarry;
}
__global__ void k_dinv() {
    int i = blockIdx.x * blockDim.x + threadIdx.x;
    if (i < NN) g_dinv[i] = rsqrtf((float)(g_deg[i] + 1));
}
__global__ void k_place(const int* __restrict__ ei) {
    int e = blockIdx.x * blockDim.x + threadIdx.x;
    if (e < EE) {
        int d = ei[EE + e];
        int pos = atomicAdd(&g_cur[d], 1);
        g_esrc[pos] = ei[e];
    }
}

// ---------------- weight precompute: bf16 hi/lo, chunk-packed ----------------
template<int DIN, int DOUT, int NPAD, int NPADP>
__global__ void k_prepw(const float* __restrict__ Wb, const float* __restrict__ Ws,
                        __nv_bfloat16* __restrict__ dst) {
    constexpr int NCH = DIN * 5 / 32;
    int idx = blockIdx.x * blockDim.x + threadIdx.x;
    if (idx >= NCH * 2 * 32 * NPADP) return;
    int n = idx % NPADP;
    int k = (idx / NPADP) & 31;
    int h = (idx / (NPADP * 32)) & 1;
    int c = idx / (NPADP * 32 * 2);
    int kg = c * 32 + k;
    float w = 0.f;
    if (n < DOUT) {
        if (kg < DIN) w = Wb[(size_t)n * DIN + kg];
        else          w = Ws[(size_t)n * (DIN * 4) + (kg - DIN)];
    }
    __nv_bfloat16 hi = __float2bfloat16(w);
    __nv_bfloat16 lo = __float2bfloat16(w - __bfloat162float(hi));
    dst[idx] = h ? lo : hi;
}

// ---------------- stats of x (warp per node): mu0/rs0 + partials ----------------
__global__ void k_statx(const float* __restrict__ x) {
    int gw = (blockIdx.x * blockDim.x + threadIdx.x) >> 5;
    int lane = threadIdx.x & 31;
    if (gw >= NN) return;
    float4 v = ((const float4*)(x + (size_t)gw * 128))[lane];
    float s  = v.x + v.y + v.z + v.w;
    float s2 = v.x * v.x + v.y * v.y + v.z * v.z + v.w * v.w;
    #pragma unroll
    for (int d = 16; d; d >>= 1) {
        s  += __shfl_xor_sync(0xffffffffu, s,  d);
        s2 += __shfl_xor_sync(0xffffffffu, s2, d);
    }
    if (lane == 0) {
        float m = s * (1.f / 128.f);
        g_mu[gw] = m;
        g_rs[gw] = rsqrtf(s2 * (1.f / 128.f) - m * m + 1e-5f);
        g_sA[gw]  = s;
        g_sA2[gw] = s2;
    }
}

// ---------------- fused FastKAN layer via wmma bf16 (3-term compensation) ----------------
__device__ __forceinline__ void splitstore(__nv_bfloat16* hiP, __nv_bfloat16* loP,
                                           float4 v) {
    __nv_bfloat162 h0 = __floats2bfloat162_rn(v.x, v.y);
    __nv_bfloat162 h1 = __floats2bfloat162_rn(v.z, v.w);
    float2 f0 = __bfloat1622float2(h0);
    float2 f1 = __bfloat1622float2(h1);
    __nv_bfloat162 l0 = __floats2bfloat162_rn(v.x - f0.x, v.y - f0.y);
    __nv_bfloat162 l1 = __floats2bfloat162_rn(v.z - f1.x, v.w - f1.y);
    ((__nv_bfloat162*)hiP)[0] = h0;
    ((__nv_bfloat162*)hiP)[1] = h1;
    ((__nv_bfloat162*)loP)[0] = l0;
    ((__nv_bfloat162*)loP)[1] = l1;
}

// Double-buffered stages: [aHi TM*ALD][aLo TM*ALD][B hi+lo][xbuf TM*32 floats].
// x chunk arrives via cp.async; each thread computes the granules it fetched
// (no extra barrier needed for cp.async visibility).
template<int DIN, int DOUT, int NPAD, int NPADP, int OUT_STRIDE, int WM,
         int TM, int THREADS>
__global__ void __launch_bounds__(THREADS, 512 / THREADS)
k_fkan_wmma(const float* __restrict__ in0, const float* __restrict__ in1,
            const float* __restrict__ in2,
            const float* __restrict__ lng, const float* __restrict__ lnb,
            const __nv_bfloat16* __restrict__ wp,
            float* __restrict__ out)
{
    constexpr int NCH   = DIN * 5 / 32;
    constexpr int NT    = NPAD / 16;
    constexpr int WARPS = THREADS / 32;
    constexpr int WN    = WARPS / WM;
    constexpr int MT    = (TM / 16) / WM;
    constexpr int NTW   = NT / WN;
    static_assert(WM * WN == WARPS && MT * WM * 16 == TM && NTW * WN == NT, "tiling");
    constexpr int ALD  = 40;
    constexpr int AELE = TM * ALD;                  // bf16 elements per A plane
    constexpr int BELE = 2 * 32 * NPADP;            // bf16 elements, B hi+lo
    constexpr int XOFF = (2 * AELE + BELE) * 2;     // byte offset of xbuf in stage
    constexpr int STB  = XOFF + TM * 32 * 4;        // stage bytes

    extern __shared__ char smc[];
    const uint32_t sbase = smem_u32(smc);

    const int t = threadIdx.x;
    const int w = t >> 5;
    const int wm = w % WM, wn = w / WM;
    const int base = blockIdx.x * TM;

    // spline-row identity (row = t>>1, col-half = t&1)
    const int rsp = t >> 1, gsp = t & 1;
    int nsp = base + rsp; if (nsp >= NN) nsp = NN - 1;
    const float mu = g_mu[nsp];
    const float rs = g_rs[nsp];

    wmma::fragment<wmma::accumulator, 16, 16, 16, float> acc[MT][NTW];
    #pragma unroll
    for (int im = 0; im < MT; im++)
        #pragma unroll
        for (int in = 0; in < NTW; in++) wmma::fill_fragment(acc[im][in], 0.f);

    // ---- cp.async staging of weights ----
    auto stageB = [&](int c, int s) {
        constexpr int NV4 = BELE * 2 / 16;
        const char* src = (const char*)(wp + (size_t)c * BELE);
        const uint32_t dst = sbase + s * STB + 2 * AELE * 2;
        #pragma unroll
        for (int i = t; i < NV4; i += THREADS)
            cpasync16(dst + i * 16, src + i * 16);
    };
    // ---- cp.async staging of x chunk ----
    auto stageX = [&](int c, int s) {
        const uint32_t xdst = sbase + s * STB + XOFF;
        const int kc = c * 32;
        if (kc < DIN) {
            const float* srcp; int colbase;
            if (DIN == 128) { srcp = in0; colbase = kc; }
            else {
                int blk = kc >> 7;
                srcp = (blk == 0) ? in0 : (blk == 1) ? in1 : in2;
                colbase = kc & 127;
            }
            #pragma unroll
            for (int i = 0; i < (TM * 8) / THREADS; i++) {
                int idx = t + i * THREADS;
                int row = idx >> 3, g = idx & 7;
                int nr = base + row; if (nr >= NN) nr = NN - 1;
                cpasync16(xdst + idx * 16, srcp + (size_t)nr * 128 + colbase + g * 4);
            }
        } else {
            int xc0 = (kc - DIN) >> 2;
            const float* srcp; int colbase;
            if (DIN == 128) { srcp = in0; colbase = xc0; }
            else {
                int blk = xc0 >> 7;
                srcp = (blk == 0) ? in0 : (blk == 1) ? in1 : in2;
                colbase = xc0 & 127;
            }
            // one granule per thread: row = t>>1, g = t&1
            cpasync16(xdst + t * 16,
                      srcp + (size_t)nsp * 128 + colbase + gsp * 4);
        }
    };
    // ---- activations from staged x (each thread reads its own granules) ----
    auto computeA = [&](int c, int s) {
        __nv_bfloat16* aHi = (__nv_bfloat16*)(smc + s * STB);
        __nv_bfloat16* aLo = aHi + AELE;
        const float* xb = (const float*)(smc + s * STB + XOFF);
        const int kc = c * 32;
        if (kc < DIN) {
            #pragma unroll
            for (int i = 0; i < (TM * 8) / THREADS; i++) {
                int idx = t + i * THREADS;
                int row = idx >> 3, g = idx & 7;
                float4 xv = *(const float4*)(xb + idx * 4);
                float4 v;
                v.x = __fdividef(xv.x, 1.f + __expf(-xv.x));
                v.y = __fdividef(xv.y, 1.f + __expf(-xv.y));
                v.z = __fdividef(xv.z, 1.f + __expf(-xv.z));
                v.w = __fdividef(xv.w, 1.f + __expf(-xv.w));
                splitstore(aHi + row * ALD + g * 4, aLo + row * ALD + g * 4, v);
            }
        } else {
            float4 xv = *(const float4*)(xb + t * 4);
            const int xc = ((kc - DIN) >> 2) + gsp * 4;
            const float4 gv = *(const float4*)(lng + xc);
            const float4 bv = *(const float4*)(lnb + xc);
            float zz[4];
            zz[0] = (xv.x - mu) * rs * gv.x + bv.x;
            zz[1] = (xv.y - mu) * rs * gv.y + bv.y;
            zz[2] = (xv.z - mu) * rs * gv.z + bv.z;
            zz[3] = (xv.w - mu) * rs * gv.w + bv.w;
            #pragma unroll
            for (int i = 0; i < 4; i++) {
                // rbf chain: rbf0 = exp(-9/16 (z+2)^2); ratio = exp(3z/2) with e^{2-2k}
                const float z = zz[i];
                const float zp2 = z + 2.f;
                const float r0 = __expf(-0.5625f * zp2 * zp2);
                const float B  = __expf(1.5f * z);
                float4 v;
                v.x = r0;
                v.y = r0 * B * 7.3890560989f;
                v.z = v.y * B;
                v.w = v.z * B * 0.1353352832f;
                const int c0 = gsp * 16 + i * 4;
                splitstore(aHi + rsp * ALD + c0, aLo + rsp * ALD + c0, v);
            }
        }
    };

    // --- prologue ---
    stageB(0, 0);
    stageX(0, 0);
    CPCOMMIT();
    CPWAIT0();
    computeA(0, 0);
    __syncthreads();

    for (int c = 0; c < NCH; c++) {
        const int s = c & 1;
        if (c + 1 < NCH) {
            stageB(c + 1, 1 - s);
            stageX(c + 1, 1 - s);
            CPCOMMIT();
        }

        {
            __nv_bfloat16* aHi = (__nv_bfloat16*)(smc + s * STB);
            __nv_bfloat16* aLo = aHi + AELE;
            __nv_bfloat16* bHi = aLo + AELE;
            #pragma unroll
            for (int kk = 0; kk < 2; kk++) {
                wmma::fragment<wmma::matrix_a, 16, 16, 16, __nv_bfloat16, wmma::row_major> ah[MT], al[MT];
                #pragma unroll
                for (int im = 0; im < MT; im++) {
                    const int mrow = (wm * MT + im) * 16;
                    wmma::load_matrix_sync(ah[im], aHi + mrow * ALD + kk * 16, ALD);
                    wmma::load_matrix_sync(al[im], aLo + mrow * ALD + kk * 16, ALD);
                }
                #pragma unroll
                for (int in = 0; in < NTW; in++) {
                    const int col = (wn * NTW + in) * 16;
                    wmma::fragment<wmma::matrix_b, 16, 16, 16, __nv_bfloat16, wmma::row_major> bh, bl;
                    wmma::load_matrix_sync(bh, bHi + kk * 16 * NPADP + col, NPADP);
                    wmma::load_matrix_sync(bl, bHi + 32 * NPADP + kk * 16 * NPADP + col, NPADP);
                    #pragma unroll
                    for (int im = 0; im < MT; im++) {
                        wmma::mma_sync(acc[im][in], ah[im], bh, acc[im][in]);
                        wmma::mma_sync(acc[im][in], ah[im], bl, acc[im][in]);
                        wmma::mma_sync(acc[im][in], al[im], bh, acc[im][in]);
                    }
                }
            }
        }

        CPWAIT0();
        if (c + 1 < NCH) computeA(c + 1, 1 - s);
        __syncthreads();
    }

    // ---- epilogue: fragments straight to gmem (out buffers padded to NN2 rows) ----
    #pragma unroll
    for (int im = 0; im < MT; im++)
        #pragma unroll
        for (int in = 0; in < NTW; in++) {
            const int mrow = (wm * MT + im) * 16;
            const int col  = (wn * NTW + in) * 16;
            wmma::store_matrix_sync(out + (size_t)(base + mrow) * OUT_STRIDE + col,
                                    acc[im][in], OUT_STRIDE, wmma::mem_row_major);
        }
}

// ---------------- aggregation + fused layernorm stats ----------------
__global__ void k_agg128(const float* __restrict__ tin, float* __restrict__ outp,
                         const float* __restrict__ bs, const float* __restrict__ bb,
                         const float* __restrict__ bg, int statmode) {
    int gw = (blockIdx.x * blockDim.x + threadIdx.x) >> 5;
    int lane = threadIdx.x & 31;
    if (gw >= NN) return;
    int beg = g_rowp[gw], end = g_rowp[gw + 1];
    const float4* t4 = (const float4*)tin;
    float4 a = make_float4(0.f, 0.f, 0.f, 0.f);
    float sw = 0.f;
    int j = beg;
    for (; j + 1 < end; j += 2) {
        int s0 = g_esrc[j], s1 = g_esrc[j + 1];
        float w0 = g_dinv[s0], w1 = g_dinv[s1];
        sw += w0 + w1;
        float4 v0 = t4[(size_t)s0 * 32 + lane];
        float4 v1 = t4[(size_t)s1 * 32 + lane];
        a.x += w0 * v0.x + w1 * v1.x;
        a.y += w0 * v0.y + w1 * v1.y;
        a.z += w0 * v0.z + w1 * v1.z;
        a.w += w0 * v0.w + w1 * v1.w;
    }
    if (j < end) {
        int s0 = g_esrc[j];
        float w0 = g_dinv[s0];
        sw += w0;
        float4 v0 = t4[(size_t)s0 * 32 + lane];
        a.x += w0 * v0.x; a.y += w0 * v0.y; a.z += w0 * v0.z; a.w += w0 * v0.w;
    }
    float dn = g_dinv[gw];
    float wb = dn * (sw + dn);
    float4 sv = t4[(size_t)gw * 32 + lane];
    float4 bgv = ((const float4*)bg)[lane];
    float4 bsv = ((const float4*)bs)[lane];
    float4 bbv = ((const float4*)bb)[lane];
    float4 o;
    o.x = dn * (a.x + dn * sv.x) + (bsv.x + bbv.x) * wb + bgv.x;
    o.y = dn * (a.y + dn * sv.y) + (bsv.y + bbv.y) * wb + bgv.y;
    o.z = dn * (a.z + dn * sv.z) + (bsv.z + bbv.z) * wb + bgv.z;
    o.w = dn * (a.w + dn * sv.w) + (bsv.w + bbv.w) * wb + bgv.w;
    ((float4*)outp)[(size_t)gw * 32 + lane] = o;

    float s  = o.x + o.y + o.z + o.w;
    float s2 = o.x * o.x + o.y * o.y + o.z * o.z + o.w * o.w;
    #pragma unroll
    for (int d = 16; d; d >>= 1) {
        s  += __shfl_xor_sync(0xffffffffu, s,  d);
        s2 += __shfl_xor_sync(0xffffffffu, s2, d);
    }
    if (lane == 0) {
        if (statmode == 1) {
            float m = s * (1.f / 128.f);
            g_mu[gw] = m;
            g_rs[gw] = rsqrtf(s2 * (1.f / 128.f) - m * m + 1e-5f);
            g_sA[gw]  += s;
            g_sA2[gw] += s2;
        } else {
            float ts  = g_sA[gw]  + s;
            float ts2 = g_sA2[gw] + s2;
            float m = ts * (1.f / 384.f);
            g_mu[gw] = m;
            g_rs[gw] = rsqrtf(ts2 * (1.f / 384.f) - m * m + 1e-5f);
        }
    }
}

__global__ void k_agg47(const float* __restrict__ tin, float* __restrict__ outp,
                        const float* __restrict__ bs, const float* __restrict__ bb,
                        const float* __restrict__ bg) {
    int gw = (blockIdx.x * blockDim.x + threadIdx.x) >> 5;
    int lane = threadIdx.x & 31;
    if (gw >= NN) return;
    int beg = g_rowp[gw], end = g_rowp[gw + 1];
    float a0 = 0.f, a1 = 0.f, sw = 0.f;
    for (int j = beg; j < end; j++) {
        int s = g_esrc[j];
        float w = g_dinv[s];
        sw += w;
        const float* ts = tin + (size_t)s * 64;
        a0 += w * ts[lane];
        if (lane < 15) a1 += w * ts[32 + lane];
    }
    float dn = g_dinv[gw];
    float wb = dn * (sw + dn);
    const float* tn = tin + (size_t)gw * 64;
    outp[(size_t)gw * 47 + lane] =
        dn * (a0 + dn * tn[lane]) + (bs[lane] + bb[lane]) * wb + bg[lane];
    if (lane < 15)
        outp[(size_t)gw * 47 + 32 + lane] =
            dn * (a1 + dn * tn[32 + lane]) + (bs[32 + lane] + bb[32 + lane]) * wb + bg[32 + lane];
}

// ---------------- driver ----------------
extern "C" void kernel_launch(void* const* d_in, const int* in_sizes, int n_in,
                              void* d_out, int out_size) {
    const float* x    = (const float*)d_in[0];
    const int*   ei   = (const int*)d_in[1];
    const float* lng0 = (const float*)d_in[2];
    const float* lnb0 = (const float*)d_in[3];
    const float* Ws0  = (const float*)d_in[4];
    const float* bs0  = (const float*)d_in[5];
    const float* Wb0  = (const float*)d_in[6];
    const float* bb0  = (const float*)d_in[7];
    const float* bg0  = (const float*)d_in[8];
    const float* lng1 = (const float*)d_in[9];
    const float* lnb1 = (const float*)d_in[10];
    const float* Ws1  = (const float*)d_in[11];
    const float* bs1  = (const float*)d_in[12];
    const float* Wb1  = (const float*)d_in[13];
    const float* bb1  = (const float*)d_in[14];
    const float* bg1  = (const float*)d_in[15];
    const float* lng2 = (const float*)d_in[16];
    const float* lnb2 = (const float*)d_in[17];
    const float* Ws2  = (const float*)d_in[18];
    const float* bs2  = (const float*)d_in[19];
    const float* Wb2  = (const float*)d_in[20];
    const float* bb2  = (const float*)d_in[21];
    const float* bg2  = (const float*)d_in[22];
    float* outp = (float*)d_out;

    void *pt, *ph1, *ph2, *pt2, *pw0, *pw1, *pw2;
    cudaGetSymbolAddress(&pt,  g_t);
    cudaGetSymbolAddress(&ph1, g_h1);
    cudaGetSymbolAddress(&ph2, g_h2);
    cudaGetSymbolAddress(&pt2, g_t2);
    cudaGetSymbolAddress(&pw0, g_wb0);
    cudaGetSymbolAddress(&pw1, g_wb1);
    cudaGetSymbolAddress(&pw2, g_wb2);

    // stage bytes = (2*TM*40 + 2*32*NPADP)*2 + TM*32*4 ; double-buffered
    const int SM_L01 = 2 * ((2 * 128 * 40 + 2 * 32 * 136) * 2 + 128 * 32 * 4); // 108544
    const int SM_L2  = 2 * ((2 * 256 * 40 + 2 * 32 * 56) * 2 + 256 * 32 * 4);  // 161792
    cudaFuncSetAttribute(
        (const void*)k_fkan_wmma<128, 128, 128, 136, 128, 4, 128, 256>,
        cudaFuncAttributeMaxDynamicSharedMemorySize, SM_L01);
    cudaFuncSetAttribute(
        (const void*)k_fkan_wmma<384, 47, 48, 56, 64, 16, 256, 512>,
        cudaFuncAttributeMaxDynamicSharedMemorySize, SM_L2);

    const int FG01 = (NN + 127) / 128;        // 782
    const int FG2  = (NN + 255) / 256;        // 391
    const int SG   = (NN * 32 + 255) / 256;   // warp per node

    // launches 1-3 (ncu profiles launch #4 -> keep it fkan layer-0)
    k_statx<<<SG, 256>>>(x);
    k_prepw<128, 128, 128, 136><<<(20 * 2 * 32 * 136 + 255) / 256, 256>>>(
        Wb0, Ws0, (__nv_bfloat16*)pw0);
    k_zero_deg<<<(NN + 255) / 256, 256>>>();

    // launch #4: layer-0 fkan (PROFILED)
    k_fkan_wmma<128, 128, 128, 136, 128, 4, 128, 256><<<FG01, 256, SM_L01>>>(
        x, nullptr, nullptr, lng0, lnb0, (const __nv_bfloat16*)pw0, (float*)pt);

    // remaining prep (independent of layer-0 output)
    k_prepw<128, 128, 128, 136><<<(20 * 2 * 32 * 136 + 255) / 256, 256>>>(
        Wb1, Ws1, (__nv_bfloat16*)pw1);
    k_prepw<384, 47, 48, 56><<<(60 * 2 * 32 * 56 + 255) / 256, 256>>>(
        Wb2, Ws2, (__nv_bfloat16*)pw2);
    k_count<<<(EE + 255) / 256, 256>>>(ei);
    k_scan<<<1, 1024>>>();
    k_dinv<<<(NN + 255) / 256, 256>>>();
    k_place<<<(EE + 255) / 256, 256>>>(ei);

    k_agg128<<<SG, 256>>>((const float*)pt, (float*)ph1, bs0, bb0, bg0, 1);

    // layer 1
    k_fkan_wmma<128, 128, 128, 136, 128, 4, 128, 256><<<FG01, 256, SM_L01>>>(
        (const float*)ph1, nullptr, nullptr, lng1, lnb1, (const __nv_bfloat16*)pw1,
        (float*)pt);
    k_agg128<<<SG, 256>>>((const float*)pt, (float*)ph2, bs1, bb1, bg1, 2);

    // layer 2
    k_fkan_wmma<384, 47, 48, 56, 64, 16, 256, 512><<<FG2, 512, SM_L2>>>(
        x, (const float*)ph1, (const float*)ph2, lng2, lnb2,
        (const __nv_bfloat16*)pw2, (float*)pt2);
    k_agg47<<<SG, 256>>>((const float*)pt2, outp, bs2, bb2, bg2);
}

// round 12
// speedup vs baseline: 1.8759x; 1.7323x over previous
#include <cuda_runtime.h>
#include <cuda_fp16.h>
#include <mma.h>
#include <cstdint>
#include <math.h>

using namespace nvcuda;

#define NN 100000
#define NN2 100352   // padded row count (multiple of 256) for unguarded tile stores
#define EE 1600000
#define NB_SCAN 98   // ceil(NN/1024)

// ---------------- scratch (device globals; no runtime allocation) ----------------
__device__ int   g_deg[NN];
__device__ int   g_rowp[NN + 1];
__device__ int   g_cur[NN];
__device__ int   g_bsum[NB_SCAN];
__device__ int   g_esrc[EE];
__device__ float g_dinv[NN];
__device__ float g_mu[NN];
__device__ float g_rs[NN];
__device__ float g_sA[NN];
__device__ float g_sA2[NN];
__device__ float g_t [NN2 * 128];
__device__ float g_h1[NN2 * 128];
__device__ float g_h2[NN2 * 128];
__device__ float g_t2[NN2 * 64];
// packed fp16 weights: per chunk [32 x NPADP]
__device__ __align__(16) __half g_wh0[20 * 32 * 136];
__device__ __align__(16) __half g_wh1[20 * 32 * 136];
__device__ __align__(16) __half g_wh2[60 * 32 * 56];

// ---------------- async-copy helpers ----------------
__device__ __forceinline__ uint32_t smem_u32(const void* p) {
    uint32_t a;
    asm("{ .reg .u64 t; cvta.to.shared.u64 t, %1; cvt.u32.u64 %0, t; }"
        : "=r"(a) : "l"(p));
    return a;
}
__device__ __forceinline__ void cpasync16(uint32_t dst, const void* src) {
    asm volatile("cp.async.cg.shared.global [%0], [%1], 16;" :: "r"(dst), "l"(src));
}
#define CPCOMMIT() asm volatile("cp.async.commit_group;" ::: "memory")
#define CPWAIT0()  asm volatile("cp.async.wait_group 0;" ::: "memory")

// ---------------- graph preprocessing ----------------
__global__ void k_zero_deg() {
    int i = blockIdx.x * blockDim.x + threadIdx.x;
    if (i < NN) g_deg[i] = 0;
}
__global__ void k_count(const int* __restrict__ ei) {
    int e = blockIdx.x * blockDim.x + threadIdx.x;
    if (e < EE) atomicAdd(&g_deg[ei[EE + e]], 1);
}
// multi-block exclusive scan of g_deg
__global__ void k_scan1() {
    __shared__ int wsum[32];
    int t = threadIdx.x, lane = t & 31, wid = t >> 5;
    int i = blockIdx.x * 1024 + t;
    int v = (i < NN) ? g_deg[i] : 0;
    int x = v;
    #pragma unroll
    for (int d = 1; d < 32; d <<= 1) {
        int y = __shfl_up_sync(0xffffffffu, x, d);
        if (lane >= d) x += y;
    }
    if (lane == 31) wsum[wid] = x;
    __syncthreads();
    if (wid == 0) {
        int ws = wsum[lane];
        #pragma unroll
        for (int d = 1; d < 32; d <<= 1) {
            int y = __shfl_up_sync(0xffffffffu, ws, d);
            if (lane >= d) ws += y;
        }
        wsum[lane] = ws;
    }
    __syncthreads();
    int excl = (wid ? wsum[wid - 1] : 0) + (x - v);
    if (i < NN) g_rowp[i] = excl;
    if (t == 0) g_bsum[blockIdx.x] = wsum[31];
}
__global__ void k_scan2() {    // 1 block, 128 threads
    __shared__ int sh[128];
    int t = threadIdx.x;
    int v = (t < NB_SCAN) ? g_bsum[t] : 0;
    int x = v;
    sh[t] = x;
    __syncthreads();
    #pragma unroll
    for (int d = 1; d < 128; d <<= 1) {
        int y = (t >= d) ? sh[t - d] : 0;
        __syncthreads();
        x += y;
        sh[t] = x;
        __syncthreads();
    }
    if (t < NB_SCAN) g_bsum[t] = x - v;
    if (t == NB_SCAN - 1) g_rowp[NN] = x;
}
__global__ void k_scan3() {    // grid NB_SCAN x 1024 ; also computes dinv
    int i = blockIdx.x * 1024 + threadIdx.x;
    if (i < NN) {
        int r = g_rowp[i] + g_bsum[blockIdx.x];
        g_rowp[i] = r;
        g_cur[i]  = r;
        g_dinv[i] = rsqrtf((float)(g_deg[i] + 1));
    }
}
__global__ void k_place(const int* __restrict__ ei) {
    int e = blockIdx.x * blockDim.x + threadIdx.x;
    if (e < EE) {
        int d = ei[EE + e];
        int pos = atomicAdd(&g_cur[d], 1);
        g_esrc[pos] = ei[e];
    }
}

// ---------------- weight precompute: fp16, chunk-packed [c][k][n] ----------------
template<int DIN, int DOUT, int NPAD, int NPADP>
__global__ void k_prepw(const float* __restrict__ Wb, const float* __restrict__ Ws,
                        __half* __restrict__ dst) {
    constexpr int NCH = DIN * 5 / 32;
    int idx = blockIdx.x * blockDim.x + threadIdx.x;
    if (idx >= NCH * 32 * NPADP) return;
    int n = idx % NPADP;
    int k = (idx / NPADP) & 31;
    int c = idx / (NPADP * 32);
    int kg = c * 32 + k;
    float w = 0.f;
    if (n < DOUT) {
        if (kg < DIN) w = Wb[(size_t)n * DIN + kg];
        else          w = Ws[(size_t)n * (DIN * 4) + (kg - DIN)];
    }
    dst[idx] = __float2half_rn(w);
}

// ---------------- stats of x (warp per node): mu0/rs0 + partials ----------------
__global__ void k_statx(const float* __restrict__ x) {
    int gw = (blockIdx.x * blockDim.x + threadIdx.x) >> 5;
    int lane = threadIdx.x & 31;
    if (gw >= NN) return;
    float4 v = ((const float4*)(x + (size_t)gw * 128))[lane];
    float s  = v.x + v.y + v.z + v.w;
    float s2 = v.x * v.x + v.y * v.y + v.z * v.z + v.w * v.w;
    #pragma unroll
    for (int d = 16; d; d >>= 1) {
        s  += __shfl_xor_sync(0xffffffffu, s,  d);
        s2 += __shfl_xor_sync(0xffffffffu, s2, d);
    }
    if (lane == 0) {
        float m = s * (1.f / 128.f);
        g_mu[gw] = m;
        g_rs[gw] = rsqrtf(s2 * (1.f / 128.f) - m * m + 1e-5f);
        g_sA[gw]  = s;
        g_sA2[gw] = s2;
    }
}

// ---------------- fused FastKAN layer via wmma fp16 (single term) ----------------
__device__ __forceinline__ void halfstore(__half* p, float4 v) {
    __half2 h0 = __floats2half2_rn(v.x, v.y);
    __half2 h1 = __floats2half2_rn(v.z, v.w);
    ((__half2*)p)[0] = h0;
    ((__half2*)p)[1] = h1;
}

// Double-buffered stages: [A TM*ALD fp16][B 32*NPADP fp16][xbuf TM*32 f32].
template<int DIN, int DOUT, int NPAD, int NPADP, int OUT_STRIDE, int WM,
         int TM, int THREADS>
__global__ void __launch_bounds__(THREADS, 512 / THREADS)
k_fkan_wmma(const float* __restrict__ in0, const float* __restrict__ in1,
            const float* __restrict__ in2,
            const float* __restrict__ lng, const float* __restrict__ lnb,
            const __half* __restrict__ wp,
            float* __restrict__ out)
{
    constexpr int NCH   = DIN * 5 / 32;
    constexpr int NT    = NPAD / 16;
    constexpr int WARPS = THREADS / 32;
    constexpr int WN    = WARPS / WM;
    constexpr int MT    = (TM / 16) / WM;
    constexpr int NTW   = NT / WN;
    static_assert(WM * WN == WARPS && MT * WM * 16 == TM && NTW * WN == NT, "tiling");
    constexpr int ALD  = 40;
    constexpr int AELE = TM * ALD;                  // fp16 elements, A plane
    constexpr int BELE = 32 * NPADP;                // fp16 elements, B plane
    constexpr int XOFF = (AELE + BELE) * 2;         // byte offset of xbuf in stage
    constexpr int STB  = XOFF + TM * 32 * 4;        // stage bytes

    extern __shared__ char smc[];
    const uint32_t sbase = smem_u32(smc);

    const int t = threadIdx.x;
    const int w = t >> 5;
    const int wm = w % WM, wn = w / WM;
    const int base = blockIdx.x * TM;

    // spline-row identity (row = t>>1, col-half = t&1)
    const int rsp = t >> 1, gsp = t & 1;
    int nsp = base + rsp; if (nsp >= NN) nsp = NN - 1;
    const float mu = g_mu[nsp];
    const float rs = g_rs[nsp];

    wmma::fragment<wmma::accumulator, 16, 16, 16, float> acc[MT][NTW];
    #pragma unroll
    for (int im = 0; im < MT; im++)
        #pragma unroll
        for (int in = 0; in < NTW; in++) wmma::fill_fragment(acc[im][in], 0.f);

    // ---- cp.async staging of weights ----
    auto stageB = [&](int c, int s) {
        constexpr int NV4 = BELE * 2 / 16;
        const char* src = (const char*)(wp + (size_t)c * BELE);
        const uint32_t dst = sbase + s * STB + AELE * 2;
        #pragma unroll
        for (int i = t; i < NV4; i += THREADS)
            cpasync16(dst + i * 16, src + i * 16);
    };
    // ---- cp.async staging of x chunk ----
    auto stageX = [&](int c, int s) {
        const uint32_t xdst = sbase + s * STB + XOFF;
        const int kc = c * 32;
        if (kc < DIN) {
            const float* srcp; int colbase;
            if (DIN == 128) { srcp = in0; colbase = kc; }
            else {
                int blk = kc >> 7;
                srcp = (blk == 0) ? in0 : (blk == 1) ? in1 : in2;
                colbase = kc & 127;
            }
            #pragma unroll
            for (int i = 0; i < (TM * 8) / THREADS; i++) {
                int idx = t + i * THREADS;
                int row = idx >> 3, g = idx & 7;
                int nr = base + row; if (nr >= NN) nr = NN - 1;
                cpasync16(xdst + idx * 16, srcp + (size_t)nr * 128 + colbase + g * 4);
            }
        } else {
            int xc0 = (kc - DIN) >> 2;
            const float* srcp; int colbase;
            if (DIN == 128) { srcp = in0; colbase = xc0; }
            else {
                int blk = xc0 >> 7;
                srcp = (blk == 0) ? in0 : (blk == 1) ? in1 : in2;
                colbase = xc0 & 127;
            }
            cpasync16(xdst + t * 16, srcp + (size_t)nsp * 128 + colbase + gsp * 4);
        }
    };
    // ---- activations from staged x ----
    auto computeA = [&](int c, int s) {
        __half* aH = (__half*)(smc + s * STB);
        const float* xb = (const float*)(smc + s * STB + XOFF);
        const int kc = c * 32;
        if (kc < DIN) {
            #pragma unroll
            for (int i = 0; i < (TM * 8) / THREADS; i++) {
                int idx = t + i * THREADS;
                int row = idx >> 3, g = idx & 7;
                float4 xv = *(const float4*)(xb + idx * 4);
                float4 v;
                v.x = __fdividef(xv.x, 1.f + __expf(-xv.x));
                v.y = __fdividef(xv.y, 1.f + __expf(-xv.y));
                v.z = __fdividef(xv.z, 1.f + __expf(-xv.z));
                v.w = __fdividef(xv.w, 1.f + __expf(-xv.w));
                halfstore(aH + row * ALD + g * 4, v);
            }
        } else {
            float4 xv = *(const float4*)(xb + t * 4);
            const int xc = ((kc - DIN) >> 2) + gsp * 4;
            const float4 gv = *(const float4*)(lng + xc);
            const float4 bv = *(const float4*)(lnb + xc);
            float zz[4];
            zz[0] = (xv.x - mu) * rs * gv.x + bv.x;
            zz[1] = (xv.y - mu) * rs * gv.y + bv.y;
            zz[2] = (xv.z - mu) * rs * gv.z + bv.z;
            zz[3] = (xv.w - mu) * rs * gv.w + bv.w;
            #pragma unroll
            for (int i = 0; i < 4; i++) {
                // rbf chain: rbf0 = exp(-9/16 (z+2)^2); ratio = exp(3z/2) with e^{2-2k}
                const float z = zz[i];
                const float zp2 = z + 2.f;
                const float r0 = __expf(-0.5625f * zp2 * zp2);
                const float B  = __expf(1.5f * z);
                float4 v;
                v.x = r0;
                v.y = r0 * B * 7.3890560989f;
                v.z = v.y * B;
                v.w = v.z * B * 0.1353352832f;
                halfstore(aH + rsp * ALD + gsp * 16 + i * 4, v);
            }
        }
    };

    // --- prologue ---
    stageB(0, 0);
    stageX(0, 0);
    CPCOMMIT();
    CPWAIT0();
    computeA(0, 0);
    __syncthreads();

    for (int c = 0; c < NCH; c++) {
        const int s = c & 1;
        if (c + 1 < NCH) {
            stageB(c + 1, 1 - s);
            stageX(c + 1, 1 - s);
            CPCOMMIT();
        }

        {
            __half* aH = (__half*)(smc + s * STB);
            __half* bB = aH + AELE;
            #pragma unroll
            for (int kk = 0; kk < 2; kk++) {
                wmma::fragment<wmma::matrix_a, 16, 16, 16, __half, wmma::row_major> af[MT];
                #pragma unroll
                for (int im = 0; im < MT; im++)
                    wmma::load_matrix_sync(af[im],
                        aH + (wm * MT + im) * 16 * ALD + kk * 16, ALD);
                #pragma unroll
                for (int in = 0; in < NTW; in++) {
                    wmma::fragment<wmma::matrix_b, 16, 16, 16, __half, wmma::row_major> bf;
                    wmma::load_matrix_sync(bf,
                        bB + kk * 16 * NPADP + (wn * NTW + in) * 16, NPADP);
                    #pragma unroll
                    for (int im = 0; im < MT; im++)
                        wmma::mma_sync(acc[im][in], af[im], bf, acc[im][in]);
                }
            }
        }

        CPWAIT0();
        if (c + 1 < NCH) computeA(c + 1, 1 - s);
        __syncthreads();
    }

    // ---- epilogue: fragments straight to gmem (out buffers padded to NN2 rows) ----
    #pragma unroll
    for (int im = 0; im < MT; im++)
        #pragma unroll
        for (int in = 0; in < NTW; in++) {
            const int mrow = (wm * MT + im) * 16;
            const int col  = (wn * NTW + in) * 16;
            wmma::store_matrix_sync(out + (size_t)(base + mrow) * OUT_STRIDE + col,
                                    acc[im][in], OUT_STRIDE, wmma::mem_row_major);
        }
}

// ---------------- aggregation + fused layernorm stats ----------------
__global__ void k_agg128(const float* __restrict__ tin, float* __restrict__ outp,
                         const float* __restrict__ bs, const float* __restrict__ bb,
                         const float* __restrict__ bg, int statmode) {
    int gw = (blockIdx.x * blockDim.x + threadIdx.x) >> 5;
    int lane = threadIdx.x & 31;
    if (gw >= NN) return;
    int beg = g_rowp[gw], end = g_rowp[gw + 1];
    const float4* t4 = (const float4*)tin;
    float4 a = make_float4(0.f, 0.f, 0.f, 0.f);
    float sw = 0.f;
    int j = beg;
    for (; j + 3 < end; j += 4) {
        int s0 = g_esrc[j], s1 = g_esrc[j + 1], s2 = g_esrc[j + 2], s3 = g_esrc[j + 3];
        float w0 = g_dinv[s0], w1 = g_dinv[s1], w2 = g_dinv[s2], w3 = g_dinv[s3];
        sw += w0 + w1 + w2 + w3;
        float4 v0 = t4[(size_t)s0 * 32 + lane];
        float4 v1 = t4[(size_t)s1 * 32 + lane];
        float4 v2 = t4[(size_t)s2 * 32 + lane];
        float4 v3 = t4[(size_t)s3 * 32 + lane];
        a.x += w0 * v0.x + w1 * v1.x + w2 * v2.x + w3 * v3.x;
        a.y += w0 * v0.y + w1 * v1.y + w2 * v2.y + w3 * v3.y;
        a.z += w0 * v0.z + w1 * v1.z + w2 * v2.z + w3 * v3.z;
        a.w += w0 * v0.w + w1 * v1.w + w2 * v2.w + w3 * v3.w;
    }
    for (; j < end; j++) {
        int s0 = g_esrc[j];
        float w0 = g_dinv[s0];
        sw += w0;
        float4 v0 = t4[(size_t)s0 * 32 + lane];
        a.x += w0 * v0.x; a.y += w0 * v0.y; a.z += w0 * v0.z; a.w += w0 * v0.w;
    }
    float dn = g_dinv[gw];
    float wb = dn * (sw + dn);
    float4 sv = t4[(size_t)gw * 32 + lane];
    float4 bgv = ((const float4*)bg)[lane];
    float4 bsv = ((const float4*)bs)[lane];
    float4 bbv = ((const float4*)bb)[lane];
    float4 o;
    o.x = dn * (a.x + dn * sv.x) + (bsv.x + bbv.x) * wb + bgv.x;
    o.y = dn * (a.y + dn * sv.y) + (bsv.y + bbv.y) * wb + bgv.y;
    o.z = dn * (a.z + dn * sv.z) + (bsv.z + bbv.z) * wb + bgv.z;
    o.w = dn * (a.w + dn * sv.w) + (bsv.w + bbv.w) * wb + bgv.w;
    ((float4*)outp)[(size_t)gw * 32 + lane] = o;

    float s  = o.x + o.y + o.z + o.w;
    float s2 = o.x * o.x + o.y * o.y + o.z * o.z + o.w * o.w;
    #pragma unroll
    for (int d = 16; d; d >>= 1) {
        s  += __shfl_xor_sync(0xffffffffu, s,  d);
        s2 += __shfl_xor_sync(0xffffffffu, s2, d);
    }
    if (lane == 0) {
        if (statmode == 1) {
            float m = s * (1.f / 128.f);
            g_mu[gw] = m;
            g_rs[gw] = rsqrtf(s2 * (1.f / 128.f) - m * m + 1e-5f);
            g_sA[gw]  += s;
            g_sA2[gw] += s2;
        } else {
            float ts  = g_sA[gw]  + s;
            float ts2 = g_sA2[gw] + s2;
            float m = ts * (1.f / 384.f);
            g_mu[gw] = m;
            g_rs[gw] = rsqrtf(ts2 * (1.f / 384.f) - m * m + 1e-5f);
        }
    }
}

__global__ void k_agg47(const float* __restrict__ tin, float* __restrict__ outp,
                        const float* __restrict__ bs, const float* __restrict__ bb,
                        const float* __restrict__ bg) {
    int gw = (blockIdx.x * blockDim.x + threadIdx.x) >> 5;
    int lane = threadIdx.x & 31;
    if (gw >= NN) return;
    int beg = g_rowp[gw], end = g_rowp[gw + 1];
    float a0 = 0.f, a1 = 0.f, sw = 0.f;
    int j = beg;
    for (; j + 1 < end; j += 2) {
        int s0 = g_esrc[j], s1 = g_esrc[j + 1];
        float w0 = g_dinv[s0], w1 = g_dinv[s1];
        sw += w0 + w1;
        const float* t0 = tin + (size_t)s0 * 64;
        const float* t1 = tin + (size_t)s1 * 64;
        a0 += w0 * t0[lane] + w1 * t1[lane];
        if (lane < 15) a1 += w0 * t0[32 + lane] + w1 * t1[32 + lane];
    }
    if (j < end) {
        int s0 = g_esrc[j];
        float w0 = g_dinv[s0];
        sw += w0;
        const float* t0 = tin + (size_t)s0 * 64;
        a0 += w0 * t0[lane];
        if (lane < 15) a1 += w0 * t0[32 + lane];
    }
    float dn = g_dinv[gw];
    float wb = dn * (sw + dn);
    const float* tn = tin + (size_t)gw * 64;
    outp[(size_t)gw * 47 + lane] =
        dn * (a0 + dn * tn[lane]) + (bs[lane] + bb[lane]) * wb + bg[lane];
    if (lane < 15)
        outp[(size_t)gw * 47 + 32 + lane] =
            dn * (a1 + dn * tn[32 + lane]) + (bs[32 + lane] + bb[32 + lane]) * wb + bg[32 + lane];
}

// ---------------- driver ----------------
extern "C" void kernel_launch(void* const* d_in, const int* in_sizes, int n_in,
                              void* d_out, int out_size) {
    const float* x    = (const float*)d_in[0];
    const int*   ei   = (const int*)d_in[1];
    const float* lng0 = (const float*)d_in[2];
    const float* lnb0 = (const float*)d_in[3];
    const float* Ws0  = (const float*)d_in[4];
    const float* bs0  = (const float*)d_in[5];
    const float* Wb0  = (const float*)d_in[6];
    const float* bb0  = (const float*)d_in[7];
    const float* bg0  = (const float*)d_in[8];
    const float* lng1 = (const float*)d_in[9];
    const float* lnb1 = (const float*)d_in[10];
    const float* Ws1  = (const float*)d_in[11];
    const float* bs1  = (const float*)d_in[12];
    const float* Wb1  = (const float*)d_in[13];
    const float* bb1  = (const float*)d_in[14];
    const float* bg1  = (const float*)d_in[15];
    const float* lng2 = (const float*)d_in[16];
    const float* lnb2 = (const float*)d_in[17];
    const float* Ws2  = (const float*)d_in[18];
    const float* bs2  = (const float*)d_in[19];
    const float* Wb2  = (const float*)d_in[20];
    const float* bb2  = (const float*)d_in[21];
    const float* bg2  = (const float*)d_in[22];
    float* outp = (float*)d_out;

    void *pt, *ph1, *ph2, *pt2, *pw0, *pw1, *pw2;
    cudaGetSymbolAddress(&pt,  g_t);
    cudaGetSymbolAddress(&ph1, g_h1);
    cudaGetSymbolAddress(&ph2, g_h2);
    cudaGetSymbolAddress(&pt2, g_t2);
    cudaGetSymbolAddress(&pw0, g_wh0);
    cudaGetSymbolAddress(&pw1, g_wh1);
    cudaGetSymbolAddress(&pw2, g_wh2);

    // stage bytes = (TM*40 + 32*NPADP)*2 + TM*32*4 ; double-buffered
    const int SM_L01 = 2 * ((128 * 40 + 32 * 136) * 2 + 128 * 32 * 4);  // 70656
    const int SM_L2  = 2 * ((256 * 40 + 32 * 56) * 2 + 256 * 32 * 4);   // 113664
    cudaFuncSetAttribute(
        (const void*)k_fkan_wmma<128, 128, 128, 136, 128, 4, 128, 256>,
        cudaFuncAttributeMaxDynamicSharedMemorySize, SM_L01);
    cudaFuncSetAttribute(
        (const void*)k_fkan_wmma<384, 47, 48, 56, 64, 16, 256, 512>,
        cudaFuncAttributeMaxDynamicSharedMemorySize, SM_L2);

    const int FG01 = (NN + 127) / 128;        // 782
    const int FG2  = (NN + 255) / 256;        // 391
    const int SG   = (NN * 32 + 255) / 256;   // warp per node

    // launches 1-3 (ncu profiles launch #4 -> keep it fkan layer-0)
    k_statx<<<SG, 256>>>(x);
    k_prepw<128, 128, 128, 136><<<(20 * 32 * 136 + 255) / 256, 256>>>(
        Wb0, Ws0, (__half*)pw0);
    k_zero_deg<<<(NN + 255) / 256, 256>>>();

    // launch #4: layer-0 fkan (PROFILED)
    k_fkan_wmma<128, 128, 128, 136, 128, 4, 128, 256><<<FG01, 256, SM_L01>>>(
        x, nullptr, nullptr, lng0, lnb0, (const __half*)pw0, (float*)pt);

    // remaining prep (independent of layer-0 output)
    k_prepw<128, 128, 128, 136><<<(20 * 32 * 136 + 255) / 256, 256>>>(
        Wb1, Ws1, (__half*)pw1);
    k_prepw<384, 47, 48, 56><<<(60 * 32 * 56 + 255) / 256, 256>>>(
        Wb2, Ws2, (__half*)pw2);
    k_count<<<(EE + 255) / 256, 256>>>(ei);
    k_scan1<<<NB_SCAN, 1024>>>();
    k_scan2<<<1, 128>>>();
    k_scan3<<<NB_SCAN, 1024>>>();
    k_place<<<(EE + 255) / 256, 256>>>(ei);

    k_agg128<<<SG, 256>>>((const float*)pt, (float*)ph1, bs0, bb0, bg0, 1);

    // layer 1
    k_fkan_wmma<128, 128, 128, 136, 128, 4, 128, 256><<<FG01, 256, SM_L01>>>(
        (const float*)ph1, nullptr, nullptr, lng1, lnb1, (const __half*)pw1,
        (float*)pt);
    k_agg128<<<SG, 256>>>((const float*)pt, (float*)ph2, bs1, bb1, bg1, 2);

    // layer 2
    k_fkan_wmma<384, 47, 48, 56, 64, 16, 256, 512><<<FG2, 512, SM_L2>>>(
        x, (const float*)ph1, (const float*)ph2, lng2, lnb2,
        (const __half*)pw2, (float*)pt2);
    k_agg47<<<SG, 256>>>((const float*)pt2, outp, bs2, bb2, bg2);
}

// round 14
// speedup vs baseline: 1.9975x; 1.0648x over previous
#include <cuda_runtime.h>
#include <cuda_fp16.h>
#include <mma.h>
#include <cstdint>
#include <math.h>

using namespace nvcuda;

#define NN 100000
#define NN2 100352   // padded row count (multiple of 256) for unguarded tile stores
#define EE 1600000
#define NB_SCAN 98   // ceil(NN/1024)

// ---------------- scratch (device globals; no runtime allocation) ----------------
__device__ int   g_deg[NN];
__device__ int   g_rowp[NN + 1];
__device__ int   g_cur[NN];
__device__ int   g_bsum[NB_SCAN];
__device__ int   g_esrc[EE];
__device__ float g_dinv[NN];
__device__ float g_mu[NN];
__device__ float g_rs[NN];
__device__ float g_sA[NN];
__device__ float g_sA2[NN];
__device__ __align__(16) __half g_t [NN2 * 128];   // fp16 pre-agg intermediate
__device__ float g_h1[NN2 * 128];
__device__ float g_h2[NN2 * 128];
__device__ __align__(16) __half g_t2[NN2 * 64];
// packed fp16 weights: per chunk [32 x NPADP]
__device__ __align__(16) __half g_wh0[20 * 32 * 136];
__device__ __align__(16) __half g_wh1[20 * 32 * 136];
__device__ __align__(16) __half g_wh2[60 * 32 * 56];

// ---------------- async-copy helpers ----------------
__device__ __forceinline__ uint32_t smem_u32(const void* p) {
    uint32_t a;
    asm("{ .reg .u64 t; cvta.to.shared.u64 t, %1; cvt.u32.u64 %0, t; }"
        : "=r"(a) : "l"(p));
    return a;
}
__device__ __forceinline__ void cpasync16(uint32_t dst, const void* src) {
    asm volatile("cp.async.cg.shared.global [%0], [%1], 16;" :: "r"(dst), "l"(src));
}
#define CPCOMMIT() asm volatile("cp.async.commit_group;" ::: "memory")
#define CPWAIT0()  asm volatile("cp.async.wait_group 0;" ::: "memory")

// ---------------- graph preprocessing ----------------
__global__ void k_zero_deg() {
    int i = blockIdx.x * blockDim.x + threadIdx.x;
    if (i < NN) g_deg[i] = 0;
}
__global__ void k_count(const int* __restrict__ ei) {
    int e = blockIdx.x * blockDim.x + threadIdx.x;
    if (e < EE) atomicAdd(&g_deg[ei[EE + e]], 1);
}
__global__ void k_scan1() {
    __shared__ int wsum[32];
    int t = threadIdx.x, lane = t & 31, wid = t >> 5;
    int i = blockIdx.x * 1024 + t;
    int v = (i < NN) ? g_deg[i] : 0;
    int x = v;
    #pragma unroll
    for (int d = 1; d < 32; d <<= 1) {
        int y = __shfl_up_sync(0xffffffffu, x, d);
        if (lane >= d) x += y;
    }
    if (lane == 31) wsum[wid] = x;
    __syncthreads();
    if (wid == 0) {
        int ws = wsum[lane];
        #pragma unroll
        for (int d = 1; d < 32; d <<= 1) {
            int y = __shfl_up_sync(0xffffffffu, ws, d);
            if (lane >= d) ws += y;
        }
        wsum[lane] = ws;
    }
    __syncthreads();
    int excl = (wid ? wsum[wid - 1] : 0) + (x - v);
    if (i < NN) g_rowp[i] = excl;
    if (t == 0) g_bsum[blockIdx.x] = wsum[31];
}
__global__ void k_scan2() {
    __shared__ int sh[128];
    int t = threadIdx.x;
    int v = (t < NB_SCAN) ? g_bsum[t] : 0;
    int x = v;
    sh[t] = x;
    __syncthreads();
    #pragma unroll
    for (int d = 1; d < 128; d <<= 1) {
        int y = (t >= d) ? sh[t - d] : 0;
        __syncthreads();
        x += y;
        sh[t] = x;
        __syncthreads();
    }
    if (t < NB_SCAN) g_bsum[t] = x - v;
    if (t == NB_SCAN - 1) g_rowp[NN] = x;
}
__global__ void k_scan3() {
    int i = blockIdx.x * 1024 + threadIdx.x;
    if (i < NN) {
        int r = g_rowp[i] + g_bsum[blockIdx.x];
        g_rowp[i] = r;
        g_cur[i]  = r;
        g_dinv[i] = rsqrtf((float)(g_deg[i] + 1));
    }
}
__global__ void k_place(const int* __restrict__ ei) {
    int e = blockIdx.x * blockDim.x + threadIdx.x;
    if (e < EE) {
        int d = ei[EE + e];
        int pos = atomicAdd(&g_cur[d], 1);
        g_esrc[pos] = ei[e];
    }
}

// ---------------- weight precompute: fp16, chunk-packed [c][k][n] ----------------
template<int DIN, int DOUT, int NPAD, int NPADP>
__global__ void k_prepw(const float* __restrict__ Wb, const float* __restrict__ Ws,
                        __half* __restrict__ dst) {
    constexpr int NCH = DIN * 5 / 32;
    int idx = blockIdx.x * blockDim.x + threadIdx.x;
    if (idx >= NCH * 32 * NPADP) return;
    int n = idx % NPADP;
    int k = (idx / NPADP) & 31;
    int c = idx / (NPADP * 32);
    int kg = c * 32 + k;
    float w = 0.f;
    if (n < DOUT) {
        if (kg < DIN) w = Wb[(size_t)n * DIN + kg];
        else          w = Ws[(size_t)n * (DIN * 4) + (kg - DIN)];
    }
    dst[idx] = __float2half_rn(w);
}

// ---------------- stats of x (warp per node): mu0/rs0 + partials ----------------
__global__ void k_statx(const float* __restrict__ x) {
    int gw = (blockIdx.x * blockDim.x + threadIdx.x) >> 5;
    int lane = threadIdx.x & 31;
    if (gw >= NN) return;
    float4 v = ((const float4*)(x + (size_t)gw * 128))[lane];
    float s  = v.x + v.y + v.z + v.w;
    float s2 = v.x * v.x + v.y * v.y + v.z * v.z + v.w * v.w;
    #pragma unroll
    for (int d = 16; d; d >>= 1) {
        s  += __shfl_xor_sync(0xffffffffu, s,  d);
        s2 += __shfl_xor_sync(0xffffffffu, s2, d);
    }
    if (lane == 0) {
        float m = s * (1.f / 128.f);
        g_mu[gw] = m;
        g_rs[gw] = rsqrtf(s2 * (1.f / 128.f) - m * m + 1e-5f);
        g_sA[gw]  = s;
        g_sA2[gw] = s2;
    }
}

// ---------------- fused FastKAN layer via wmma fp16 (single term) ----------------
__device__ __forceinline__ void halfstore(__half* p, float4 v) {
    __half2 h0 = __floats2half2_rn(v.x, v.y);
    __half2 h1 = __floats2half2_rn(v.z, v.w);
    ((__half2*)p)[0] = h0;
    ((__half2*)p)[1] = h1;
}

// Double-buffered stages: [A TM*ALD fp16][B 32*NPADP fp16][xbuf TM*32 f32].
// Epilogue: acc frags -> smem (reuse stage mem) -> fp16 gmem (padded NN2 rows).
template<int DIN, int DOUT, int NPAD, int NPADP, int OUT_STRIDE, int WM,
         int TM, int THREADS>
__global__ void __launch_bounds__(THREADS, 512 / THREADS)
k_fkan_wmma(const float* __restrict__ in0, const float* __restrict__ in1,
            const float* __restrict__ in2,
            const float* __restrict__ lng, const float* __restrict__ lnb,
            const __half* __restrict__ wp,
            __half* __restrict__ out)
{
    constexpr int NCH   = DIN * 5 / 32;
    constexpr int NT    = NPAD / 16;
    constexpr int WARPS = THREADS / 32;
    constexpr int WN    = WARPS / WM;
    constexpr int MT    = (TM / 16) / WM;
    constexpr int NTW   = NT / WN;
    static_assert(WM * WN == WARPS && MT * WM * 16 == TM && NTW * WN == NT, "tiling");
    constexpr int ALD  = 40;
    constexpr int AELE = TM * ALD;
    constexpr int BELE = 32 * NPADP;
    constexpr int XOFF = (AELE + BELE) * 2;
    constexpr int STB  = XOFF + TM * 32 * 4;
    constexpr int OUTS = NPAD + 8;                  // epilogue smem stride (floats)

    extern __shared__ char smc[];
    const uint32_t sbase = smem_u32(smc);

    const int t = threadIdx.x;
    const int w = t >> 5;
    const int wm = w % WM, wn = w / WM;
    const int base = blockIdx.x * TM;

    const int rsp = t >> 1, gsp = t & 1;
    int nsp = base + rsp; if (nsp >= NN) nsp = NN - 1;
    const float mu = g_mu[nsp];
    const float rs = g_rs[nsp];

    wmma::fragment<wmma::accumulator, 16, 16, 16, float> acc[MT][NTW];
    #pragma unroll
    for (int im = 0; im < MT; im++)
        #pragma unroll
        for (int in = 0; in < NTW; in++) wmma::fill_fragment(acc[im][in], 0.f);

    auto stageB = [&](int c, int s) {
        constexpr int NV4 = BELE * 2 / 16;
        const char* src = (const char*)(wp + (size_t)c * BELE);
        const uint32_t dst = sbase + s * STB + AELE * 2;
        #pragma unroll
        for (int i = t; i < NV4; i += THREADS)
            cpasync16(dst + i * 16, src + i * 16);
    };
    auto stageX = [&](int c, int s) {
        const uint32_t xdst = sbase + s * STB + XOFF;
        const int kc = c * 32;
        if (kc < DIN) {
            const float* srcp; int colbase;
            if (DIN == 128) { srcp = in0; colbase = kc; }
            else {
                int blk = kc >> 7;
                srcp = (blk == 0) ? in0 : (blk == 1) ? in1 : in2;
                colbase = kc & 127;
            }
            #pragma unroll
            for (int i = 0; i < (TM * 8) / THREADS; i++) {
                int idx = t + i * THREADS;
                int row = idx >> 3, g = idx & 7;
                int nr = base + row; if (nr >= NN) nr = NN - 1;
                cpasync16(xdst + idx * 16, srcp + (size_t)nr * 128 + colbase + g * 4);
            }
        } else {
            int xc0 = (kc - DIN) >> 2;
            const float* srcp; int colbase;
            if (DIN == 128) { srcp = in0; colbase = xc0; }
            else {
                int blk = xc0 >> 7;
                srcp = (blk == 0) ? in0 : (blk == 1) ? in1 : in2;
                colbase = xc0 & 127;
            }
            cpasync16(xdst + t * 16, srcp + (size_t)nsp * 128 + colbase + gsp * 4);
        }
    };
    auto computeA = [&](int c, int s) {
        __half* aH = (__half*)(smc + s * STB);
        const float* xb = (const float*)(smc + s * STB + XOFF);
        const int kc = c * 32;
        if (kc < DIN) {
            #pragma unroll
            for (int i = 0; i < (TM * 8) / THREADS; i++) {
                int idx = t + i * THREADS;
                int row = idx >> 3, g = idx & 7;
                float4 xv = *(const float4*)(xb + idx * 4);
                float4 v;
                v.x = __fdividef(xv.x, 1.f + __expf(-xv.x));
                v.y = __fdividef(xv.y, 1.f + __expf(-xv.y));
                v.z = __fdividef(xv.z, 1.f + __expf(-xv.z));
                v.w = __fdividef(xv.w, 1.f + __expf(-xv.w));
                halfstore(aH + row * ALD + g * 4, v);
            }
        } else {
            float4 xv = *(const float4*)(xb + t * 4);
            const int xc = ((kc - DIN) >> 2) + gsp * 4;
            const float4 gv = *(const float4*)(lng + xc);
            const float4 bv = *(const float4*)(lnb + xc);
            float zz[4];
            zz[0] = (xv.x - mu) * rs * gv.x + bv.x;
            zz[1] = (xv.y - mu) * rs * gv.y + bv.y;
            zz[2] = (xv.z - mu) * rs * gv.z + bv.z;
            zz[3] = (xv.w - mu) * rs * gv.w + bv.w;
            #pragma unroll
            for (int i = 0; i < 4; i++) {
                const float z = zz[i];
                const float zp2 = z + 2.f;
                const float r0 = __expf(-0.5625f * zp2 * zp2);
                const float B  = __expf(1.5f * z);
                float4 v;
                v.x = r0;
                v.y = r0 * B * 7.3890560989f;
                v.z = v.y * B;
                v.w = v.z * B * 0.1353352832f;
                halfstore(aH + rsp * ALD + gsp * 16 + i * 4, v);
            }
        }
    };

    stageB(0, 0);
    stageX(0, 0);
    CPCOMMIT();
    CPWAIT0();
    computeA(0, 0);
    __syncthreads();

    for (int c = 0; c < NCH; c++) {
        const int s = c & 1;
        if (c + 1 < NCH) {
            stageB(c + 1, 1 - s);
            stageX(c + 1, 1 - s);
            CPCOMMIT();
        }

        {
            __half* aH = (__half*)(smc + s * STB);
            __half* bB = aH + AELE;
            #pragma unroll
            for (int kk = 0; kk < 2; kk++) {
                wmma::fragment<wmma::matrix_a, 16, 16, 16, __half, wmma::row_major> af[MT];
                #pragma unroll
                for (int im = 0; im < MT; im++)
                    wmma::load_matrix_sync(af[im],
                        aH + (wm * MT + im) * 16 * ALD + kk * 16, ALD);
                #pragma unroll
                for (int in = 0; in < NTW; in++) {
                    wmma::fragment<wmma::matrix_b, 16, 16, 16, __half, wmma::row_major> bf;
                    wmma::load_matrix_sync(bf,
                        bB + kk * 16 * NPADP + (wn * NTW + in) * 16, NPADP);
                    #pragma unroll
                    for (int im = 0; im < MT; im++)
                        wmma::mma_sync(acc[im][in], af[im], bf, acc[im][in]);
                }
            }
        }

        CPWAIT0();
        if (c + 1 < NCH) computeA(c + 1, 1 - s);
        __syncthreads();
    }

    // ---- epilogue: acc -> smem (float) -> fp16 gmem ----
    float* sOut = (float*)smc;
    #pragma unroll
    for (int im = 0; im < MT; im++)
        #pragma unroll
        for (int in = 0; in < NTW; in++)
            wmma::store_matrix_sync(
                sOut + ((wm * MT + im) * 16) * OUTS + (wn * NTW + in) * 16,
                acc[im][in], OUTS, wmma::mem_row_major);
    __syncthreads();

    constexpr int HP = NPAD / 2;   // half2 per row
    for (int e = t; e < TM * HP; e += THREADS) {
        int row = e / HP, j = e % HP;
        const float* sp = sOut + row * OUTS + j * 2;
        __half2 h = __floats2half2_rn(sp[0], sp[1]);
        *(__half2*)(out + (size_t)(base + row) * OUT_STRIDE + j * 2) = h;
    }
}

// ---------------- aggregation (fp16 gather) + fused layernorm stats ----------------
__global__ void k_agg128(const __half* __restrict__ tin, float* __restrict__ outp,
                         const float* __restrict__ bs, const float* __restrict__ bb,
                         const float* __restrict__ bg, int statmode) {
    int gw = (blockIdx.x * blockDim.x + threadIdx.x) >> 5;
    int lane = threadIdx.x & 31;
    if (gw >= NN) return;
    int beg = g_rowp[gw], end = g_rowp[gw + 1];
    float4 a = make_float4(0.f, 0.f, 0.f, 0.f);
    float sw = 0.f;
    int j = beg;
    for (; j + 3 < end; j += 4) {
        int s0 = g_esrc[j], s1 = g_esrc[j + 1], s2 = g_esrc[j + 2], s3 = g_esrc[j + 3];
        float w0 = g_dinv[s0], w1 = g_dinv[s1], w2 = g_dinv[s2], w3 = g_dinv[s3];
        sw += w0 + w1 + w2 + w3;
        uint2 u0 = ((const uint2*)(tin + (size_t)s0 * 128))[lane];
        uint2 u1 = ((const uint2*)(tin + (size_t)s1 * 128))[lane];
        uint2 u2 = ((const uint2*)(tin + (size_t)s2 * 128))[lane];
        uint2 u3 = ((const uint2*)(tin + (size_t)s3 * 128))[lane];
        float2 f0a = __half22float2(*(__half2*)&u0.x), f0b = __half22float2(*(__half2*)&u0.y);
        float2 f1a = __half22float2(*(__half2*)&u1.x), f1b = __half22float2(*(__half2*)&u1.y);
        float2 f2a = __half22float2(*(__half2*)&u2.x), f2b = __half22float2(*(__half2*)&u2.y);
        float2 f3a = __half22float2(*(__half2*)&u3.x), f3b = __half22float2(*(__half2*)&u3.y);
        a.x += w0 * f0a.x + w1 * f1a.x + w2 * f2a.x + w3 * f3a.x;
        a.y += w0 * f0a.y + w1 * f1a.y + w2 * f2a.y + w3 * f3a.y;
        a.z += w0 * f0b.x + w1 * f1b.x + w2 * f2b.x + w3 * f3b.x;
        a.w += w0 * f0b.y + w1 * f1b.y + w2 * f2b.y + w3 * f3b.y;
    }
    for (; j < end; j++) {
        int s0 = g_esrc[j];
        float w0 = g_dinv[s0];
        sw += w0;
        uint2 u0 = ((const uint2*)(tin + (size_t)s0 * 128))[lane];
        float2 f0a = __half22float2(*(__half2*)&u0.x), f0b = __half22float2(*(__half2*)&u0.y);
        a.x += w0 * f0a.x; a.y += w0 * f0a.y; a.z += w0 * f0b.x; a.w += w0 * f0b.y;
    }
    float dn = g_dinv[gw];
    float wb = dn * (sw + dn);
    uint2 us = ((const uint2*)(tin + (size_t)gw * 128))[lane];
    float2 fsa = __half22float2(*(__half2*)&us.x), fsb = __half22float2(*(__half2*)&us.y);
    float4 bgv = ((const float4*)bg)[lane];
    float4 bsv = ((const float4*)bs)[lane];
    float4 bbv = ((const float4*)bb)[lane];
    float4 o;
    o.x = dn * (a.x + dn * fsa.x) + (bsv.x + bbv.x) * wb + bgv.x;
    o.y = dn * (a.y + dn * fsa.y) + (bsv.y + bbv.y) * wb + bgv.y;
    o.z = dn * (a.z + dn * fsb.x) + (bsv.z + bbv.z) * wb + bgv.z;
    o.w = dn * (a.w + dn * fsb.y) + (bsv.w + bbv.w) * wb + bgv.w;
    ((float4*)outp)[(size_t)gw * 32 + lane] = o;

    float s  = o.x + o.y + o.z + o.w;
    float s2 = o.x * o.x + o.y * o.y + o.z * o.z + o.w * o.w;
    #pragma unroll
    for (int d = 16; d; d >>= 1) {
        s  += __shfl_xor_sync(0xffffffffu, s,  d);
        s2 += __shfl_xor_sync(0xffffffffu, s2, d);
    }
    if (lane == 0) {
        if (statmode == 1) {
            float m = s * (1.f / 128.f);
            g_mu[gw] = m;
            g_rs[gw] = rsqrtf(s2 * (1.f / 128.f) - m * m + 1e-5f);
            g_sA[gw]  += s;
            g_sA2[gw] += s2;
        } else {
            float ts  = g_sA[gw]  + s;
            float ts2 = g_sA2[gw] + s2;
            float m = ts * (1.f / 384.f);
            g_mu[gw] = m;
            g_rs[gw] = rsqrtf(ts2 * (1.f / 384.f) - m * m + 1e-5f);
        }
    }
}

// lane handles column pair (2*lane, 2*lane+1) of the 64-wide fp16 rows;
// lanes >= 24 (c0 >= 48 > 47) contribute nothing (writes guarded).
__global__ void k_agg47(const __half* __restrict__ tin, float* __restrict__ outp,
                        const float* __restrict__ bs, const float* __restrict__ bb,
                        const float* __restrict__ bg) {
    int gw = (blockIdx.x * blockDim.x + threadIdx.x) >> 5;
    int lane = threadIdx.x & 31;
    if (gw >= NN) return;
    int beg = g_rowp[gw], end = g_rowp[gw + 1];
    float a0 = 0.f, a1 = 0.f, sw = 0.f;
    int j = beg;
    for (; j + 1 < end; j += 2) {
        int s0 = g_esrc[j], s1 = g_esrc[j + 1];
        float w0 = g_dinv[s0], w1 = g_dinv[s1];
        sw += w0 + w1;
        float2 f0 = __half22float2(((const __half2*)(tin + (size_t)s0 * 64))[lane]);
        float2 f1 = __half22float2(((const __half2*)(tin + (size_t)s1 * 64))[lane]);
        a0 += w0 * f0.x + w1 * f1.x;
        a1 += w0 * f0.y + w1 * f1.y;
    }
    if (j < end) {
        int s0 = g_esrc[j];
        float w0 = g_dinv[s0];
        sw += w0;
        float2 f0 = __half22float2(((const __half2*)(tin + (size_t)s0 * 64))[lane]);
        a0 += w0 * f0.x;
        a1 += w0 * f0.y;
    }
    float dn = g_dinv[gw];
    float wb = dn * (sw + dn);
    float2 fs = __half22float2(((const __half2*)(tin + (size_t)gw * 64))[lane]);
    int c0 = lane * 2, c1 = c0 + 1;
    if (c0 < 47)
        outp[(size_t)gw * 47 + c0] =
            dn * (a0 + dn * fs.x) + (bs[c0] + bb[c0]) * wb + bg[c0];
    if (c1 < 47)
        outp[(size_t)gw * 47 + c1] =
            dn * (a1 + dn * fs.y) + (bs[c1] + bb[c1]) * wb + bg[c1];
}

// ---------------- driver ----------------
extern "C" void kernel_launch(void* const* d_in, const int* in_sizes, int n_in,
                              void* d_out, int out_size) {
    const float* x    = (const float*)d_in[0];
    const int*   ei   = (const int*)d_in[1];
    const float* lng0 = (const float*)d_in[2];
    const float* lnb0 = (const float*)d_in[3];
    const float* Ws0  = (const float*)d_in[4];
    const float* bs0  = (const float*)d_in[5];
    const float* Wb0  = (const float*)d_in[6];
    const float* bb0  = (const float*)d_in[7];
    const float* bg0  = (const float*)d_in[8];
    const float* lng1 = (const float*)d_in[9];
    const float* lnb1 = (const float*)d_in[10];
    const float* Ws1  = (const float*)d_in[11];
    const float* bs1  = (const float*)d_in[12];
    const float* Wb1  = (const float*)d_in[13];
    const float* bb1  = (const float*)d_in[14];
    const float* bg1  = (const float*)d_in[15];
    const float* lng2 = (const float*)d_in[16];
    const float* lnb2 = (const float*)d_in[17];
    const float* Ws2  = (const float*)d_in[18];
    const float* bs2  = (const float*)d_in[19];
    const float* Wb2  = (const float*)d_in[20];
    const float* bb2  = (const float*)d_in[21];
    const float* bg2  = (const float*)d_in[22];
    float* outp = (float*)d_out;

    void *pt, *ph1, *ph2, *pt2, *pw0, *pw1, *pw2;
    cudaGetSymbolAddress(&pt,  g_t);
    cudaGetSymbolAddress(&ph1, g_h1);
    cudaGetSymbolAddress(&ph2, g_h2);
    cudaGetSymbolAddress(&pt2, g_t2);
    cudaGetSymbolAddress(&pw0, g_wh0);
    cudaGetSymbolAddress(&pw1, g_wh1);
    cudaGetSymbolAddress(&pw2, g_wh2);

    // smem: stage = (TM*40 + 32*NPADP)*2 + TM*32*4, doubled; epilogue = TM*(NPAD+8)*4
    const int STG_L01 = 2 * ((128 * 40 + 32 * 136) * 2 + 128 * 32 * 4);  // 70656
    const int EPI_L01 = 128 * 136 * 4;                                    // 69632
    const int SM_L01  = STG_L01 > EPI_L01 ? STG_L01 : EPI_L01;
    const int STG_L2  = 2 * ((256 * 40 + 32 * 56) * 2 + 256 * 32 * 4);   // 113664
    const int EPI_L2  = 256 * 56 * 4;                                     // 57344
    const int SM_L2   = STG_L2 > EPI_L2 ? STG_L2 : EPI_L2;
    cudaFuncSetAttribute(
        (const void*)k_fkan_wmma<128, 128, 128, 136, 128, 4, 128, 256>,
        cudaFuncAttributeMaxDynamicSharedMemorySize, SM_L01);
    cudaFuncSetAttribute(
        (const void*)k_fkan_wmma<384, 47, 48, 56, 64, 16, 256, 512>,
        cudaFuncAttributeMaxDynamicSharedMemorySize, SM_L2);

    const int FG01 = (NN + 127) / 128;        // 782
    const int FG2  = (NN + 255) / 256;        // 391
    const int SG   = (NN * 32 + 255) / 256;   // warp per node

    // launches 1-3 (ncu profiles launch #4 -> keep it fkan layer-0)
    k_statx<<<SG, 256>>>(x);
    k_prepw<128, 128, 128, 136><<<(20 * 32 * 136 + 255) / 256, 256>>>(
        Wb0, Ws0, (__half*)pw0);
    k_zero_deg<<<(NN + 255) / 256, 256>>>();

    // launch #4: layer-0 fkan (PROFILED)
    k_fkan_wmma<128, 128, 128, 136, 128, 4, 128, 256><<<FG01, 256, SM_L01>>>(
        x, nullptr, nullptr, lng0, lnb0, (const __half*)pw0, (__half*)pt);

    // remaining prep (independent of layer-0 output)
    k_prepw<128, 128, 128, 136><<<(20 * 32 * 136 + 255) / 256, 256>>>(
        Wb1, Ws1, (__half*)pw1);
    k_prepw<384, 47, 48, 56><<<(60 * 32 * 56 + 255) / 256, 256>>>(
        Wb2, Ws2, (__half*)pw2);
    k_count<<<(EE + 255) / 256, 256>>>(ei);
    k_scan1<<<NB_SCAN, 1024>>>();
    k_scan2<<<1, 128>>>();
    k_scan3<<<NB_SCAN, 1024>>>();
    k_place<<<(EE + 255) / 256, 256>>>(ei);

    k_agg128<<<SG, 256>>>((const __half*)pt, (float*)ph1, bs0, bb0, bg0, 1);

    // layer 1
    k_fkan_wmma<128, 128, 128, 136, 128, 4, 128, 256><<<FG01, 256, SM_L01>>>(
        (const float*)ph1, nullptr, nullptr, lng1, lnb1, (const __half*)pw1,
        (__half*)pt);
    k_agg128<<<SG, 256>>>((const __half*)pt, (float*)ph2, bs1, bb1, bg1, 2);

    // layer 2
    k_fkan_wmma<384, 47, 48, 56, 64, 16, 256, 512><<<FG2, 512, SM_L2>>>(
        x, (const float*)ph1, (const float*)ph2, lng2, lnb2,
        (const __half*)pw2, (__half*)pt2);
    k_agg47<<<SG, 256>>>((const __half*)pt2, outp, bs2, bb2, bg2);
}

// round 15
// speedup vs baseline: 2.1498x; 1.0762x over previous
#include <cuda_runtime.h>
#include <cuda_fp16.h>
#include <mma.h>
#include <cstdint>
#include <math.h>

using namespace nvcuda;

#define NN 100000
#define NN2 100352   // padded row count (multiple of 256) for unguarded tile stores
#define EE 1600000
#define NB_SCAN 98   // ceil(NN/1024)

// ---------------- scratch (device globals; no runtime allocation) ----------------
__device__ int   g_deg[NN];
__device__ int   g_rowp[NN + 1];
__device__ int   g_cur[NN];
__device__ int   g_bsum[NB_SCAN];
__device__ int   g_esrc[EE];
__device__ float g_dinv[NN];
__device__ float g_mu[NN];
__device__ float g_rs[NN];
__device__ float g_sA[NN];
__device__ float g_sA2[NN];
__device__ __align__(16) __half g_t [NN2 * 128];   // fp16 pre-agg intermediate
__device__ float g_h1[NN2 * 128];
__device__ float g_h2[NN2 * 128];
__device__ __align__(16) __half g_t2[NN2 * 64];
// packed fp16 weights: per chunk [32 x NPADP]
__device__ __align__(16) __half g_wh0[20 * 32 * 136];
__device__ __align__(16) __half g_wh1[20 * 32 * 136];
__device__ __align__(16) __half g_wh2[60 * 32 * 56];

// ---------------- async-copy helpers ----------------
__device__ __forceinline__ uint32_t smem_u32(const void* p) {
    uint32_t a;
    asm("{ .reg .u64 t; cvta.to.shared.u64 t, %1; cvt.u32.u64 %0, t; }"
        : "=r"(a) : "l"(p));
    return a;
}
__device__ __forceinline__ void cpasync16(uint32_t dst, const void* src) {
    asm volatile("cp.async.cg.shared.global [%0], [%1], 16;" :: "r"(dst), "l"(src));
}
#define CPCOMMIT() asm volatile("cp.async.commit_group;" ::: "memory")
#define CPWAIT0()  asm volatile("cp.async.wait_group 0;" ::: "memory")

// ---------------- graph preprocessing ----------------
__global__ void k_zero_deg() {
    int i = blockIdx.x * blockDim.x + threadIdx.x;
    if (i < NN) g_deg[i] = 0;
}
// 4 edges per thread, int4 reads of the dst half
__global__ void k_count(const int* __restrict__ ei) {
    int e4 = blockIdx.x * blockDim.x + threadIdx.x;
    if (e4 * 4 >= EE) return;
    int4 d = ((const int4*)(ei + EE))[e4];
    atomicAdd(&g_deg[d.x], 1);
    atomicAdd(&g_deg[d.y], 1);
    atomicAdd(&g_deg[d.z], 1);
    atomicAdd(&g_deg[d.w], 1);
}
__global__ void k_scan1() {
    __shared__ int wsum[32];
    int t = threadIdx.x, lane = t & 31, wid = t >> 5;
    int i = blockIdx.x * 1024 + t;
    int v = (i < NN) ? g_deg[i] : 0;
    int x = v;
    #pragma unroll
    for (int d = 1; d < 32; d <<= 1) {
        int y = __shfl_up_sync(0xffffffffu, x, d);
        if (lane >= d) x += y;
    }
    if (lane == 31) wsum[wid] = x;
    __syncthreads();
    if (wid == 0) {
        int ws = wsum[lane];
        #pragma unroll
        for (int d = 1; d < 32; d <<= 1) {
            int y = __shfl_up_sync(0xffffffffu, ws, d);
            if (lane >= d) ws += y;
        }
        wsum[lane] = ws;
    }
    __syncthreads();
    int excl = (wid ? wsum[wid - 1] : 0) + (x - v);
    if (i < NN) g_rowp[i] = excl;
    if (t == 0) g_bsum[blockIdx.x] = wsum[31];
}
__global__ void k_scan2() {
    __shared__ int sh[128];
    int t = threadIdx.x;
    int v = (t < NB_SCAN) ? g_bsum[t] : 0;
    int x = v;
    sh[t] = x;
    __syncthreads();
    #pragma unroll
    for (int d = 1; d < 128; d <<= 1) {
        int y = (t >= d) ? sh[t - d] : 0;
        __syncthreads();
        x += y;
        sh[t] = x;
        __syncthreads();
    }
    if (t < NB_SCAN) g_bsum[t] = x - v;
    if (t == NB_SCAN - 1) g_rowp[NN] = x;
}
__global__ void k_scan3() {
    int i = blockIdx.x * 1024 + threadIdx.x;
    if (i < NN) {
        int r = g_rowp[i] + g_bsum[blockIdx.x];
        g_rowp[i] = r;
        g_cur[i]  = r;
        g_dinv[i] = rsqrtf((float)(g_deg[i] + 1));
    }
}
// 4 edges per thread, int4 reads of both halves
__global__ void k_place(const int* __restrict__ ei) {
    int e4 = blockIdx.x * blockDim.x + threadIdx.x;
    if (e4 * 4 >= EE) return;
    int4 s = ((const int4*)ei)[e4];
    int4 d = ((const int4*)(ei + EE))[e4];
    g_esrc[atomicAdd(&g_cur[d.x], 1)] = s.x;
    g_esrc[atomicAdd(&g_cur[d.y], 1)] = s.y;
    g_esrc[atomicAdd(&g_cur[d.z], 1)] = s.z;
    g_esrc[atomicAdd(&g_cur[d.w], 1)] = s.w;
}

// ---------------- weight precompute: fp16, chunk-packed [c][k][n] ----------------
template<int DIN, int DOUT, int NPAD, int NPADP>
__global__ void k_prepw(const float* __restrict__ Wb, const float* __restrict__ Ws,
                        __half* __restrict__ dst) {
    constexpr int NCH = DIN * 5 / 32;
    int idx = blockIdx.x * blockDim.x + threadIdx.x;
    if (idx >= NCH * 32 * NPADP) return;
    int n = idx % NPADP;
    int k = (idx / NPADP) & 31;
    int c = idx / (NPADP * 32);
    int kg = c * 32 + k;
    float w = 0.f;
    if (n < DOUT) {
        if (kg < DIN) w = Wb[(size_t)n * DIN + kg];
        else          w = Ws[(size_t)n * (DIN * 4) + (kg - DIN)];
    }
    dst[idx] = __float2half_rn(w);
}

// ---------------- stats of x (warp per node): mu0/rs0 + partials ----------------
__global__ void k_statx(const float* __restrict__ x) {
    int gw = (blockIdx.x * blockDim.x + threadIdx.x) >> 5;
    int lane = threadIdx.x & 31;
    if (gw >= NN) return;
    float4 v = ((const float4*)(x + (size_t)gw * 128))[lane];
    float s  = v.x + v.y + v.z + v.w;
    float s2 = v.x * v.x + v.y * v.y + v.z * v.z + v.w * v.w;
    #pragma unroll
    for (int d = 16; d; d >>= 1) {
        s  += __shfl_xor_sync(0xffffffffu, s,  d);
        s2 += __shfl_xor_sync(0xffffffffu, s2, d);
    }
    if (lane == 0) {
        float m = s * (1.f / 128.f);
        g_mu[gw] = m;
        g_rs[gw] = rsqrtf(s2 * (1.f / 128.f) - m * m + 1e-5f);
        g_sA[gw]  = s;
        g_sA2[gw] = s2;
    }
}

// ---------------- fused FastKAN layer via wmma fp16 (single term) ----------------
__device__ __forceinline__ void halfstore(__half* p, float4 v) {
    __half2 h0 = __floats2half2_rn(v.x, v.y);
    __half2 h1 = __floats2half2_rn(v.z, v.w);
    ((__half2*)p)[0] = h0;
    ((__half2*)p)[1] = h1;
}

// Double-buffered stages: [A TM*ALD fp16][B 32*NPADP fp16][xbuf TM*32 f32].
// Epilogue: acc frags -> smem (reuse stage mem) -> fp16 gmem (padded NN2 rows).
template<int DIN, int DOUT, int NPAD, int NPADP, int OUT_STRIDE, int WM,
         int TM, int THREADS>
__global__ void __launch_bounds__(THREADS, 512 / THREADS)
k_fkan_wmma(const float* __restrict__ in0, const float* __restrict__ in1,
            const float* __restrict__ in2,
            const float* __restrict__ lng, const float* __restrict__ lnb,
            const __half* __restrict__ wp,
            __half* __restrict__ out)
{
    constexpr int NCH   = DIN * 5 / 32;
    constexpr int NT    = NPAD / 16;
    constexpr int WARPS = THREADS / 32;
    constexpr int WN    = WARPS / WM;
    constexpr int MT    = (TM / 16) / WM;
    constexpr int NTW   = NT / WN;
    static_assert(WM * WN == WARPS && MT * WM * 16 == TM && NTW * WN == NT, "tiling");
    constexpr int ALD  = 40;
    constexpr int AELE = TM * ALD;
    constexpr int BELE = 32 * NPADP;
    constexpr int XOFF = (AELE + BELE) * 2;
    constexpr int STB  = XOFF + TM * 32 * 4;
    constexpr int OUTS = NPAD + 8;                  // epilogue smem stride (floats)

    extern __shared__ char smc[];
    const uint32_t sbase = smem_u32(smc);

    const int t = threadIdx.x;
    const int w = t >> 5;
    const int wm = w % WM, wn = w / WM;
    const int base = blockIdx.x * TM;

    const int rsp = t >> 1, gsp = t & 1;
    int nsp = base + rsp; if (nsp >= NN) nsp = NN - 1;
    const float mu = g_mu[nsp];
    const float rs = g_rs[nsp];

    wmma::fragment<wmma::accumulator, 16, 16, 16, float> acc[MT][NTW];
    #pragma unroll
    for (int im = 0; im < MT; im++)
        #pragma unroll
        for (int in = 0; in < NTW; in++) wmma::fill_fragment(acc[im][in], 0.f);

    auto stageB = [&](int c, int s) {
        constexpr int NV4 = BELE * 2 / 16;
        const char* src = (const char*)(wp + (size_t)c * BELE);
        const uint32_t dst = sbase + s * STB + AELE * 2;
        #pragma unroll
        for (int i = t; i < NV4; i += THREADS)
            cpasync16(dst + i * 16, src + i * 16);
    };
    auto stageX = [&](int c, int s) {
        const uint32_t xdst = sbase + s * STB + XOFF;
        const int kc = c * 32;
        if (kc < DIN) {
            const float* srcp; int colbase;
            if (DIN == 128) { srcp = in0; colbase = kc; }
            else {
                int blk = kc >> 7;
                srcp = (blk == 0) ? in0 : (blk == 1) ? in1 : in2;
                colbase = kc & 127;
            }
            #pragma unroll
            for (int i = 0; i < (TM * 8) / THREADS; i++) {
                int idx = t + i * THREADS;
                int row = idx >> 3, g = idx & 7;
                int nr = base + row; if (nr >= NN) nr = NN - 1;
                cpasync16(xdst + idx * 16, srcp + (size_t)nr * 128 + colbase + g * 4);
            }
        } else {
            int xc0 = (kc - DIN) >> 2;
            const float* srcp; int colbase;
            if (DIN == 128) { srcp = in0; colbase = xc0; }
            else {
                int blk = xc0 >> 7;
                srcp = (blk == 0) ? in0 : (blk == 1) ? in1 : in2;
                colbase = xc0 & 127;
            }
            cpasync16(xdst + t * 16, srcp + (size_t)nsp * 128 + colbase + gsp * 4);
        }
    };
    auto computeA = [&](int c, int s) {
        __half* aH = (__half*)(smc + s * STB);
        const float* xb = (const float*)(smc + s * STB + XOFF);
        const int kc = c * 32;
        if (kc < DIN) {
            #pragma unroll
            for (int i = 0; i < (TM * 8) / THREADS; i++) {
                int idx = t + i * THREADS;
                int row = idx >> 3, g = idx & 7;
                float4 xv = *(const float4*)(xb + idx * 4);
                float4 v;
                v.x = __fdividef(xv.x, 1.f + __expf(-xv.x));
                v.y = __fdividef(xv.y, 1.f + __expf(-xv.y));
                v.z = __fdividef(xv.z, 1.f + __expf(-xv.z));
                v.w = __fdividef(xv.w, 1.f + __expf(-xv.w));
                halfstore(aH + row * ALD + g * 4, v);
            }
        } else {
            float4 xv = *(const float4*)(xb + t * 4);
            const int xc = ((kc - DIN) >> 2) + gsp * 4;
            const float4 gv = *(const float4*)(lng + xc);
            const float4 bv = *(const float4*)(lnb + xc);
            float zz[4];
            zz[0] = (xv.x - mu) * rs * gv.x + bv.x;
            zz[1] = (xv.y - mu) * rs * gv.y + bv.y;
            zz[2] = (xv.z - mu) * rs * gv.z + bv.z;
            zz[3] = (xv.w - mu) * rs * gv.w + bv.w;
            #pragma unroll
            for (int i = 0; i < 4; i++) {
                const float z = zz[i];
                const float zp2 = z + 2.f;
                const float r0 = __expf(-0.5625f * zp2 * zp2);
                const float B  = __expf(1.5f * z);
                float4 v;
                v.x = r0;
                v.y = r0 * B * 7.3890560989f;
                v.z = v.y * B;
                v.w = v.z * B * 0.1353352832f;
                halfstore(aH + rsp * ALD + gsp * 16 + i * 4, v);
            }
        }
    };

    stageB(0, 0);
    stageX(0, 0);
    CPCOMMIT();
    CPWAIT0();
    computeA(0, 0);
    __syncthreads();

    for (int c = 0; c < NCH; c++) {
        const int s = c & 1;
        if (c + 1 < NCH) {
            stageB(c + 1, 1 - s);
            stageX(c + 1, 1 - s);
            CPCOMMIT();
        }

        {
            __half* aH = (__half*)(smc + s * STB);
            __half* bB = aH + AELE;
            #pragma unroll
            for (int kk = 0; kk < 2; kk++) {
                wmma::fragment<wmma::matrix_a, 16, 16, 16, __half, wmma::row_major> af[MT];
                #pragma unroll
                for (int im = 0; im < MT; im++)
                    wmma::load_matrix_sync(af[im],
                        aH + (wm * MT + im) * 16 * ALD + kk * 16, ALD);
                #pragma unroll
                for (int in = 0; in < NTW; in++) {
                    wmma::fragment<wmma::matrix_b, 16, 16, 16, __half, wmma::row_major> bf;
                    wmma::load_matrix_sync(bf,
                        bB + kk * 16 * NPADP + (wn * NTW + in) * 16, NPADP);
                    #pragma unroll
                    for (int im = 0; im < MT; im++)
                        wmma::mma_sync(acc[im][in], af[im], bf, acc[im][in]);
                }
            }
        }

        CPWAIT0();
        if (c + 1 < NCH) computeA(c + 1, 1 - s);
        __syncthreads();
    }

    // ---- epilogue: acc -> smem (float) -> fp16 gmem ----
    float* sOut = (float*)smc;
    #pragma unroll
    for (int im = 0; im < MT; im++)
        #pragma unroll
        for (int in = 0; in < NTW; in++)
            wmma::store_matrix_sync(
                sOut + ((wm * MT + im) * 16) * OUTS + (wn * NTW + in) * 16,
                acc[im][in], OUTS, wmma::mem_row_major);
    __syncthreads();

    constexpr int HP = NPAD / 2;   // half2 per row
    for (int e = t; e < TM * HP; e += THREADS) {
        int row = e / HP, j = e % HP;
        const float* sp = sOut + row * OUTS + j * 2;
        __half2 h = __floats2half2_rn(sp[0], sp[1]);
        *(__half2*)(out + (size_t)(base + row) * OUT_STRIDE + j * 2) = h;
    }
}

// ---------------- aggregation (fp16 gather, 8-deep unroll) + fused stats ----------------
__global__ void k_agg128(const __half* __restrict__ tin, float* __restrict__ outp,
                         const float* __restrict__ bs, const float* __restrict__ bb,
                         const float* __restrict__ bg, int statmode) {
    int gw = (blockIdx.x * blockDim.x + threadIdx.x) >> 5;
    int lane = threadIdx.x & 31;
    if (gw >= NN) return;
    int beg = g_rowp[gw], end = g_rowp[gw + 1];
    float4 a = make_float4(0.f, 0.f, 0.f, 0.f);
    float sw = 0.f;
    int j = beg;
    for (; j + 7 < end; j += 8) {
        int   si[8];
        float wi[8];
        uint2 ui[8];
        #pragma unroll
        for (int q = 0; q < 8; q++) si[q] = g_esrc[j + q];
        #pragma unroll
        for (int q = 0; q < 8; q++) {
            wi[q] = g_dinv[si[q]];
            ui[q] = ((const uint2*)(tin + (size_t)si[q] * 128))[lane];
        }
        #pragma unroll
        for (int q = 0; q < 8; q++) {
            sw += wi[q];
            float2 fa = __half22float2(*(__half2*)&ui[q].x);
            float2 fb = __half22float2(*(__half2*)&ui[q].y);
            a.x += wi[q] * fa.x;
            a.y += wi[q] * fa.y;
            a.z += wi[q] * fb.x;
            a.w += wi[q] * fb.y;
        }
    }
    for (; j < end; j++) {
        int s0 = g_esrc[j];
        float w0 = g_dinv[s0];
        sw += w0;
        uint2 u0 = ((const uint2*)(tin + (size_t)s0 * 128))[lane];
        float2 f0a = __half22float2(*(__half2*)&u0.x), f0b = __half22float2(*(__half2*)&u0.y);
        a.x += w0 * f0a.x; a.y += w0 * f0a.y; a.z += w0 * f0b.x; a.w += w0 * f0b.y;
    }
    float dn = g_dinv[gw];
    float wb = dn * (sw + dn);
    uint2 us = ((const uint2*)(tin + (size_t)gw * 128))[lane];
    float2 fsa = __half22float2(*(__half2*)&us.x), fsb = __half22float2(*(__half2*)&us.y);
    float4 bgv = ((const float4*)bg)[lane];
    float4 bsv = ((const float4*)bs)[lane];
    float4 bbv = ((const float4*)bb)[lane];
    float4 o;
    o.x = dn * (a.x + dn * fsa.x) + (bsv.x + bbv.x) * wb + bgv.x;
    o.y = dn * (a.y + dn * fsa.y) + (bsv.y + bbv.y) * wb + bgv.y;
    o.z = dn * (a.z + dn * fsb.x) + (bsv.z + bbv.z) * wb + bgv.z;
    o.w = dn * (a.w + dn * fsb.y) + (bsv.w + bbv.w) * wb + bgv.w;
    ((float4*)outp)[(size_t)gw * 32 + lane] = o;

    float s  = o.x + o.y + o.z + o.w;
    float s2 = o.x * o.x + o.y * o.y + o.z * o.z + o.w * o.w;
    #pragma unroll
    for (int d = 16; d; d >>= 1) {
        s  += __shfl_xor_sync(0xffffffffu, s,  d);
        s2 += __shfl_xor_sync(0xffffffffu, s2, d);
    }
    if (lane == 0) {
        if (statmode == 1) {
            float m = s * (1.f / 128.f);
            g_mu[gw] = m;
            g_rs[gw] = rsqrtf(s2 * (1.f / 128.f) - m * m + 1e-5f);
            g_sA[gw]  += s;
            g_sA2[gw] += s2;
        } else {
            float ts  = g_sA[gw]  + s;
            float ts2 = g_sA2[gw] + s2;
            float m = ts * (1.f / 384.f);
            g_mu[gw] = m;
            g_rs[gw] = rsqrtf(ts2 * (1.f / 384.f) - m * m + 1e-5f);
        }
    }
}

// lane handles column pair (2*lane, 2*lane+1); lanes >= 24 guarded out.
__global__ void k_agg47(const __half* __restrict__ tin, float* __restrict__ outp,
                        const float* __restrict__ bs, const float* __restrict__ bb,
                        const float* __restrict__ bg) {
    int gw = (blockIdx.x * blockDim.x + threadIdx.x) >> 5;
    int lane = threadIdx.x & 31;
    if (gw >= NN) return;
    int beg = g_rowp[gw], end = g_rowp[gw + 1];
    float a0 = 0.f, a1 = 0.f, sw = 0.f;
    int j = beg;
    for (; j + 3 < end; j += 4) {
        int s0 = g_esrc[j], s1 = g_esrc[j + 1], s2 = g_esrc[j + 2], s3 = g_esrc[j + 3];
        float w0 = g_dinv[s0], w1 = g_dinv[s1], w2 = g_dinv[s2], w3 = g_dinv[s3];
        sw += w0 + w1 + w2 + w3;
        float2 f0 = __half22float2(((const __half2*)(tin + (size_t)s0 * 64))[lane]);
        float2 f1 = __half22float2(((const __half2*)(tin + (size_t)s1 * 64))[lane]);
        float2 f2 = __half22float2(((const __half2*)(tin + (size_t)s2 * 64))[lane]);
        float2 f3 = __half22float2(((const __half2*)(tin + (size_t)s3 * 64))[lane]);
        a0 += w0 * f0.x + w1 * f1.x + w2 * f2.x + w3 * f3.x;
        a1 += w0 * f0.y + w1 * f1.y + w2 * f2.y + w3 * f3.y;
    }
    for (; j < end; j++) {
        int s0 = g_esrc[j];
        float w0 = g_dinv[s0];
        sw += w0;
        float2 f0 = __half22float2(((const __half2*)(tin + (size_t)s0 * 64))[lane]);
        a0 += w0 * f0.x;
        a1 += w0 * f0.y;
    }
    float dn = g_dinv[gw];
    float wb = dn * (sw + dn);
    float2 fs = __half22float2(((const __half2*)(tin + (size_t)gw * 64))[lane]);
    int c0 = lane * 2, c1 = c0 + 1;
    if (c0 < 47)
        outp[(size_t)gw * 47 + c0] =
            dn * (a0 + dn * fs.x) + (bs[c0] + bb[c0]) * wb + bg[c0];
    if (c1 < 47)
        outp[(size_t)gw * 47 + c1] =
            dn * (a1 + dn * fs.y) + (bs[c1] + bb[c1]) * wb + bg[c1];
}

// ---------------- driver ----------------
extern "C" void kernel_launch(void* const* d_in, const int* in_sizes, int n_in,
                              void* d_out, int out_size) {
    const float* x    = (const float*)d_in[0];
    const int*   ei   = (const int*)d_in[1];
    const float* lng0 = (const float*)d_in[2];
    const float* lnb0 = (const float*)d_in[3];
    const float* Ws0  = (const float*)d_in[4];
    const float* bs0  = (const float*)d_in[5];
    const float* Wb0  = (const float*)d_in[6];
    const float* bb0  = (const float*)d_in[7];
    const float* bg0  = (const float*)d_in[8];
    const float* lng1 = (const float*)d_in[9];
    const float* lnb1 = (const float*)d_in[10];
    const float* Ws1  = (const float*)d_in[11];
    const float* bs1  = (const float*)d_in[12];
    const float* Wb1  = (const float*)d_in[13];
    const float* bb1  = (const float*)d_in[14];
    const float* bg1  = (const float*)d_in[15];
    const float* lng2 = (const float*)d_in[16];
    const float* lnb2 = (const float*)d_in[17];
    const float* Ws2  = (const float*)d_in[18];
    const float* bs2  = (const float*)d_in[19];
    const float* Wb2  = (const float*)d_in[20];
    const float* bb2  = (const float*)d_in[21];
    const float* bg2  = (const float*)d_in[22];
    float* outp = (float*)d_out;

    void *pt, *ph1, *ph2, *pt2, *pw0, *pw1, *pw2;
    cudaGetSymbolAddress(&pt,  g_t);
    cudaGetSymbolAddress(&ph1, g_h1);
    cudaGetSymbolAddress(&ph2, g_h2);
    cudaGetSymbolAddress(&pt2, g_t2);
    cudaGetSymbolAddress(&pw0, g_wh0);
    cudaGetSymbolAddress(&pw1, g_wh1);
    cudaGetSymbolAddress(&pw2, g_wh2);

    // smem: stage = (TM*40 + 32*NPADP)*2 + TM*32*4, doubled; epilogue = TM*(NPAD+8)*4
    const int STG_L01 = 2 * ((128 * 40 + 32 * 136) * 2 + 128 * 32 * 4);  // 70656
    const int EPI_L01 = 128 * 136 * 4;                                    // 69632
    const int SM_L01  = STG_L01 > EPI_L01 ? STG_L01 : EPI_L01;
    const int STG_L2  = 2 * ((128 * 40 + 32 * 56) * 2 + 128 * 32 * 4);   // 60416
    const int EPI_L2  = 128 * 56 * 4;                                     // 28672
    const int SM_L2   = STG_L2 > EPI_L2 ? STG_L2 : EPI_L2;
    cudaFuncSetAttribute(
        (const void*)k_fkan_wmma<128, 128, 128, 136, 128, 4, 128, 256>,
        cudaFuncAttributeMaxDynamicSharedMemorySize, SM_L01);
    cudaFuncSetAttribute(
        (const void*)k_fkan_wmma<384, 47, 48, 56, 64, 8, 128, 256>,
        cudaFuncAttributeMaxDynamicSharedMemorySize, SM_L2);

    const int FG01 = (NN + 127) / 128;        // 782
    const int SG   = (NN * 32 + 255) / 256;   // warp per node
    const int EG4  = (EE / 4 + 255) / 256;    // 4 edges per thread

    // launches 1-3 (ncu profiles launch #4 -> keep it fkan layer-0)
    k_statx<<<SG, 256>>>(x);
    k_prepw<128, 128, 128, 136><<<(20 * 32 * 136 + 255) / 256, 256>>>(
        Wb0, Ws0, (__half*)pw0);
    k_zero_deg<<<(NN + 255) / 256, 256>>>();

    // launch #4: layer-0 fkan (PROFILED)
    k_fkan_wmma<128, 128, 128, 136, 128, 4, 128, 256><<<FG01, 256, SM_L01>>>(
        x, nullptr, nullptr, lng0, lnb0, (const __half*)pw0, (__half*)pt);

    // remaining prep (independent of layer-0 output)
    k_prepw<128, 128, 128, 136><<<(20 * 32 * 136 + 255) / 256, 256>>>(
        Wb1, Ws1, (__half*)pw1);
    k_prepw<384, 47, 48, 56><<<(60 * 32 * 56 + 255) / 256, 256>>>(
        Wb2, Ws2, (__half*)pw2);
    k_count<<<EG4, 256>>>(ei);
    k_scan1<<<NB_SCAN, 1024>>>();
    k_scan2<<<1, 128>>>();
    k_scan3<<<NB_SCAN, 1024>>>();
    k_place<<<EG4, 256>>>(ei);

    k_agg128<<<SG, 256>>>((const __half*)pt, (float*)ph1, bs0, bb0, bg0, 1);

    // layer 1
    k_fkan_wmma<128, 128, 128, 136, 128, 4, 128, 256><<<FG01, 256, SM_L01>>>(
        (const float*)ph1, nullptr, nullptr, lng1, lnb1, (const __half*)pw1,
        (__half*)pt);
    k_agg128<<<SG, 256>>>((const __half*)pt, (float*)ph2, bs1, bb1, bg1, 2);

    // layer 2 (now TM=128, 256 threads, 2 CTAs/SM)
    k_fkan_wmma<384, 47, 48, 56, 64, 8, 128, 256><<<FG01, 256, SM_L2>>>(
        x, (const float*)ph1, (const float*)ph2, lng2, lnb2,
        (const __half*)pw2, (__half*)pt2);
    k_agg47<<<SG, 256>>>((const __half*)pt2, outp, bs2, bb2, bg2);
}